// round 1
// baseline (speedup 1.0000x reference)
#include <cuda_runtime.h>
#include <cstdint>

#define DMODEL 1024
#define NSEQ   1024
#define NHEADS 16     // contracted axis per d-slice
#define NDSLICE 64    // 1024 / 16

static const int MN = DMODEL * NSEQ;

// ---------------- scratch (device globals; no allocs allowed) ----------------
__device__ float g_Q[2 * DMODEL * NSEQ];
__device__ float g_K[2 * DMODEL * NSEQ];
__device__ float g_V[2 * DMODEL * NSEQ];
__device__ float g_X[2 * DMODEL * NSEQ];

// ---------------- tf32 GEMM:  Y = W @ X + bias (+ R) ----------------
// W: [1024,1024] row-major (o, c) ; X: [1024,1024] row-major (c, n)

struct GemmDesc { const float *W, *bias, *X, *R; float *Y; };
struct GemmBatch { GemmDesc g[6]; };

__device__ __forceinline__ uint32_t f2tf32(float f) {
    uint32_t r;
    asm("cvt.rna.tf32.f32 %0, %1;" : "=r"(r) : "f"(f));
    return r;
}

constexpr int BM = 128, BN = 128, BK = 32;

__global__ __launch_bounds__(256, 2) void conv_gemm(GemmBatch batch) {
    const GemmDesc gd = batch.g[blockIdx.z];

    __shared__ uint32_t As[BK][BM + 4];   // A^T: [k][m], pitch 132 -> conflict-free frag loads
    __shared__ uint32_t Bs[BK][BN + 4];   // B:   [k][n], pitch 132

    const int tid  = threadIdx.x;
    const int lane = tid & 31;
    const int warp = tid >> 5;
    const int gq   = lane >> 2;   // groupID (0..7)
    const int tg   = lane & 3;    // threadID_in_group (0..3)
    const int wm   = (warp >> 2) * 64;   // warp row base within block tile
    const int wn   = (warp & 3) * 32;    // warp col base
    const int bm0  = blockIdx.x * BM;
    const int bn0  = blockIdx.y * BN;

    float acc[4][4][4];
#pragma unroll
    for (int mi = 0; mi < 4; mi++)
#pragma unroll
        for (int ni = 0; ni < 4; ni++)
#pragma unroll
            for (int r = 0; r < 4; r++) acc[mi][ni][r] = 0.f;

    for (int k0 = 0; k0 < DMODEL; k0 += BK) {
        // --- load A tile (W rows bm0..bm0+127, cols k0..k0+31), store transposed [k][m]
#pragma unroll
        for (int i = 0; i < 4; i++) {
            int idx = tid + i * 256;          // 1024 float4s
            int r = idx >> 3, c4 = idx & 7;
            const float4 w = *(const float4*)(gd.W + (size_t)(bm0 + r) * DMODEL + k0 + c4 * 4);
            As[c4 * 4 + 0][r] = f2tf32(w.x);
            As[c4 * 4 + 1][r] = f2tf32(w.y);
            As[c4 * 4 + 2][r] = f2tf32(w.z);
            As[c4 * 4 + 3][r] = f2tf32(w.w);
        }
        // --- load B tile (X rows k0..k0+31, cols bn0..bn0+127) row-major [k][n]
#pragma unroll
        for (int i = 0; i < 4; i++) {
            int idx = tid + i * 256;
            int r = idx >> 5, c4 = idx & 31;
            const float4 x = *(const float4*)(gd.X + (size_t)(k0 + r) * NSEQ + bn0 + c4 * 4);
            uint4 u;
            u.x = f2tf32(x.x); u.y = f2tf32(x.y); u.z = f2tf32(x.z); u.w = f2tf32(x.w);
            *(uint4*)&Bs[r][c4 * 4] = u;
        }
        __syncthreads();

#pragma unroll
        for (int kk = 0; kk < BK; kk += 8) {
            uint32_t af[4][4], bf[4][2];
#pragma unroll
            for (int mi = 0; mi < 4; mi++) {
                int m0 = wm + mi * 16 + gq;
                af[mi][0] = As[kk + tg][m0];
                af[mi][1] = As[kk + tg][m0 + 8];
                af[mi][2] = As[kk + tg + 4][m0];
                af[mi][3] = As[kk + tg + 4][m0 + 8];
            }
#pragma unroll
            for (int ni = 0; ni < 4; ni++) {
                int n0 = wn + ni * 8 + gq;
                bf[ni][0] = Bs[kk + tg][n0];
                bf[ni][1] = Bs[kk + tg + 4][n0];
            }
#pragma unroll
            for (int mi = 0; mi < 4; mi++)
#pragma unroll
                for (int ni = 0; ni < 4; ni++)
                    asm volatile(
                        "mma.sync.aligned.m16n8k8.row.col.f32.tf32.tf32.f32 "
                        "{%0,%1,%2,%3}, {%4,%5,%6,%7}, {%8,%9}, {%0,%1,%2,%3};"
                        : "+f"(acc[mi][ni][0]), "+f"(acc[mi][ni][1]),
                          "+f"(acc[mi][ni][2]), "+f"(acc[mi][ni][3])
                        : "r"(af[mi][0]), "r"(af[mi][1]), "r"(af[mi][2]), "r"(af[mi][3]),
                          "r"(bf[ni][0]), "r"(bf[ni][1]));
        }
        __syncthreads();
    }

    // --- epilogue: bias + optional residual
#pragma unroll
    for (int mi = 0; mi < 4; mi++) {
        int row0 = bm0 + wm + mi * 16 + gq;
        int row1 = row0 + 8;
        float b0 = gd.bias[row0], b1 = gd.bias[row1];
#pragma unroll
        for (int ni = 0; ni < 4; ni++) {
            int col = bn0 + wn + ni * 8 + tg * 2;
            size_t i0 = (size_t)row0 * NSEQ + col;
            size_t i1 = (size_t)row1 * NSEQ + col;
            float v00 = acc[mi][ni][0] + b0, v01 = acc[mi][ni][1] + b0;
            float v10 = acc[mi][ni][2] + b1, v11 = acc[mi][ni][3] + b1;
            if (gd.R) {
                v00 += gd.R[i0]; v01 += gd.R[i0 + 1];
                v10 += gd.R[i1]; v11 += gd.R[i1 + 1];
            }
            gd.Y[i0] = v00; gd.Y[i0 + 1] = v01;
            gd.Y[i1] = v10; gd.Y[i1 + 1] = v11;
        }
    }
}

// ---------------- fused flash attention over d-slices ----------------
// For each d: scores[n,m] = (1/8) * sum_h Q[d*16+h, n] * K[d*16+h, m]
//             p = softmax_m(scores) ; X[d*16+h, n] = sum_m V[d*16+h, m] * p[n,m]
// No max subtraction needed: |scores| is tiny (<< 80), exp cannot overflow,
// ratio is mathematically identical to the max-subtracted softmax.

__global__ __launch_bounds__(128) void flash_kernel(const float* __restrict__ Qb,
                                                    const float* __restrict__ Kb,
                                                    const float* __restrict__ Vb,
                                                    float* __restrict__ Xb) {
    extern __shared__ float sm[];
    float* Ks = sm;                // [16][1024]
    float* Vs = sm + 16 * NSEQ;    // [16][1024]

    const int item  = blockIdx.z;
    const int d     = blockIdx.x;
    const int nbase = blockIdx.y * 512;
    const int tid   = threadIdx.x;

    const float* Q = Qb + (size_t)item * (DMODEL * NSEQ);
    const float* K = Kb + (size_t)item * (DMODEL * NSEQ);
    const float* V = Vb + (size_t)item * (DMODEL * NSEQ);
    float*       X = Xb + (size_t)item * (DMODEL * NSEQ);

    const float* Kg = K + (size_t)(d * 16) * NSEQ;
    const float* Vg = V + (size_t)(d * 16) * NSEQ;

    // fill K/V tiles: 4096 float4 each, coalesced, conflict-free
#pragma unroll
    for (int j = 0; j < 32; j++) {
        int idx = tid + j * 128;
        *(float4*)&Ks[idx * 4] = *(const float4*)&Kg[idx * 4];
    }
#pragma unroll
    for (int j = 0; j < 32; j++) {
        int idx = tid + j * 128;
        *(float4*)&Vs[idx * 4] = *(const float4*)&Vg[idx * 4];
    }
    __syncthreads();

    // 4 query rows per thread, scale 1/sqrt(64) folded into q
    float q[4][16];
#pragma unroll
    for (int r = 0; r < 4; r++) {
        int n = nbase + tid + r * 128;
#pragma unroll
        for (int h = 0; h < 16; h++)
            q[r][h] = Q[(size_t)(d * 16 + h) * NSEQ + n] * 0.125f;
    }

    float acc[4][16];
    float l[4] = {0.f, 0.f, 0.f, 0.f};
#pragma unroll
    for (int r = 0; r < 4; r++)
#pragma unroll
        for (int h = 0; h < 16; h++) acc[r][h] = 0.f;

#pragma unroll 1
    for (int m = 0; m < NSEQ; m++) {
        float kh[16];
#pragma unroll
        for (int h = 0; h < 16; h++) kh[h] = Ks[h * NSEQ + m];   // warp broadcast

        float s[4];
#pragma unroll
        for (int r = 0; r < 4; r++) {
            float t = q[r][0] * kh[0];
#pragma unroll
            for (int h = 1; h < 16; h++) t = fmaf(q[r][h], kh[h], t);
            s[r] = t;
        }

        float vh[16];
#pragma unroll
        for (int h = 0; h < 16; h++) vh[h] = Vs[h * NSEQ + m];

#pragma unroll
        for (int r = 0; r < 4; r++) {
            float p = __expf(s[r]);
            l[r] += p;
#pragma unroll
            for (int h = 0; h < 16; h++) acc[r][h] = fmaf(p, vh[h], acc[r][h]);
        }
    }

#pragma unroll
    for (int r = 0; r < 4; r++) {
        float inv = 1.0f / l[r];
        int n = nbase + tid + r * 128;
#pragma unroll
        for (int h = 0; h < 16; h++)
            X[(size_t)(d * 16 + h) * NSEQ + n] = acc[r][h] * inv;
    }
}

// ---------------- launch ----------------
extern "C" void kernel_launch(void* const* d_in, const int* in_sizes, int n_in,
                              void* d_out, int out_size) {
    (void)in_sizes; (void)n_in; (void)out_size;

    const float* desc0 = (const float*)d_in[0];
    const float* desc1 = (const float*)d_in[1];
    const float* Wq = (const float*)d_in[2]; const float* bq = (const float*)d_in[3];
    const float* Wk = (const float*)d_in[4]; const float* bk = (const float*)d_in[5];
    const float* Wv = (const float*)d_in[6]; const float* bv = (const float*)d_in[7];
    const float* Wm = (const float*)d_in[8]; const float* bm = (const float*)d_in[9];

    float* out0 = (float*)d_out;
    float* out1 = out0 + MN;

    float *Qb, *Kb, *Vb, *Xb;
    cudaGetSymbolAddress((void**)&Qb, g_Q);
    cudaGetSymbolAddress((void**)&Kb, g_K);
    cudaGetSymbolAddress((void**)&Vb, g_V);
    cudaGetSymbolAddress((void**)&Xb, g_X);

    cudaFuncSetAttribute(flash_kernel, cudaFuncAttributeMaxDynamicSharedMemorySize, 131072);

    // ---- attn1 (desc0 self) + attn2 (desc1 self): QKV
    GemmBatch A{};
    A.g[0] = {Wq, bq, desc0, nullptr, Qb};
    A.g[1] = {Wk, bk, desc0, nullptr, Kb};
    A.g[2] = {Wv, bv, desc0, nullptr, Vb};
    A.g[3] = {Wq, bq, desc1, nullptr, Qb + MN};
    A.g[4] = {Wk, bk, desc1, nullptr, Kb + MN};
    A.g[5] = {Wv, bv, desc1, nullptr, Vb + MN};
    conv_gemm<<<dim3(8, 8, 6), 256>>>(A);

    flash_kernel<<<dim3(64, 2, 2), 128, 131072>>>(Qb, Kb, Vb, Xb);

    // d0 = desc0 + Wm@X0 + bm ; d1 = desc1 + Wm@X1 + bm  (into d_out)
    GemmBatch C{};
    C.g[0] = {Wm, bm, Xb,      desc0, out0};
    C.g[1] = {Wm, bm, Xb + MN, desc1, out1};
    conv_gemm<<<dim3(8, 8, 2), 256>>>(C);

    // ---- attn3: q=d0, kv=d1
    GemmBatch D{};
    D.g[0] = {Wq, bq, out0, nullptr, Qb};
    D.g[1] = {Wk, bk, out1, nullptr, Kb};
    D.g[2] = {Wv, bv, out1, nullptr, Vb};
    conv_gemm<<<dim3(8, 8, 3), 256>>>(D);

    flash_kernel<<<dim3(64, 2, 1), 128, 131072>>>(Qb, Kb, Vb, Xb);

    GemmBatch F{};
    F.g[0] = {Wm, bm, Xb, out0, out0};   // d0 += conv(x)
    conv_gemm<<<dim3(8, 8, 1), 256>>>(F);

    // ---- attn4: q=d1, kv=d0(new)
    GemmBatch G{};
    G.g[0] = {Wq, bq, out1, nullptr, Qb};
    G.g[1] = {Wk, bk, out0, nullptr, Kb};
    G.g[2] = {Wv, bv, out0, nullptr, Vb};
    conv_gemm<<<dim3(8, 8, 3), 256>>>(G);

    flash_kernel<<<dim3(64, 2, 1), 128, 131072>>>(Qb, Kb, Vb, Xb);

    GemmBatch I{};
    I.g[0] = {Wm, bm, Xb, out1, out1};   // d1 += conv(x)
    conv_gemm<<<dim3(8, 8, 1), 256>>>(I);
}

// round 2
// speedup vs baseline: 1.9450x; 1.9450x over previous
#include <cuda_runtime.h>
#include <cstdint>

#define DMODEL 1024
#define NSEQ   1024
static const int MN = DMODEL * NSEQ;

// ---------------- scratch (device globals; no allocs allowed) ----------------
__device__ float g_Q[2 * 1024 * 1024];
__device__ float g_K[2 * 1024 * 1024];
__device__ float g_V[2 * 1024 * 1024];
__device__ float g_X[2 * 1024 * 1024];
__device__ float g_W[4 * 1024 * 1024];   // tf32-rounded weights
__device__ float g_D[2 * 1024 * 1024];   // tf32-rounded desc0/desc1
__device__ float g_T[2 * 1024 * 1024];   // tf32-rounded copies of out0/out1

__device__ __forceinline__ uint32_t f2tf32(float f) {
    uint32_t r;
    asm("cvt.rna.tf32.f32 %0, %1;" : "=r"(r) : "f"(f));
    return r;
}
__device__ __forceinline__ float ex2f(float x) {
    float y;
    asm("ex2.approx.f32 %0, %1;" : "=f"(y) : "f"(x));
    return y;
}
__device__ __forceinline__ void mma_tf32(float* d, const uint32_t* a, uint32_t b0, uint32_t b1) {
    asm volatile(
        "mma.sync.aligned.m16n8k8.row.col.f32.tf32.tf32.f32 "
        "{%0,%1,%2,%3}, {%4,%5,%6,%7}, {%8,%9}, {%0,%1,%2,%3};"
        : "+f"(d[0]), "+f"(d[1]), "+f"(d[2]), "+f"(d[3])
        : "r"(a[0]), "r"(a[1]), "r"(a[2]), "r"(a[3]), "r"(b0), "r"(b1));
}
__device__ __forceinline__ void cp16(void* dst, const void* src) {
    uint32_t d = (uint32_t)__cvta_generic_to_shared(dst);
    asm volatile("cp.async.cg.shared.global [%0], [%1], 16;" :: "r"(d), "l"(src));
}
#define CP_COMMIT() asm volatile("cp.async.commit_group;")
#define CP_WAIT1()  asm volatile("cp.async.wait_group 1;")

// ---------------- prep: tf32-round W matrices and descs ----------------
struct CvtBatch { const float* s[6]; float* d[6]; };

__global__ __launch_bounds__(256) void prep_kernel(CvtBatch cb) {
    const float4* s = (const float4*)cb.s[blockIdx.y];
    uint4*        d = (uint4*)cb.d[blockIdx.y];
    int i = blockIdx.x * 256 + threadIdx.x;
    float4 v = s[i];
    uint4 u;
    u.x = f2tf32(v.x); u.y = f2tf32(v.y); u.z = f2tf32(v.z); u.w = f2tf32(v.w);
    d[i] = u;
}

// ---------------- tf32 GEMM with cp.async 3-stage pipeline ----------------
// Y = W @ X + bias (+ R). W,X are PRE-ROUNDED to the tf32 grid (no cvt in loop).
// W: [1024,1024] row-major (m,k) ; X: [1024,1024] row-major (k,n)

struct GemmDesc { const float *W, *bias, *X, *R; float *Y, *Ytf; };
struct GemmBatch { GemmDesc g[6]; };

constexpr int BK = 32;
constexpr int PA = 36;                 // A smem pitch (floats): [m][k]
constexpr int PB = 132;                // B smem pitch (floats): [k][n]
constexpr int ASTG = 128 * PA;         // 4608 floats / stage
constexpr int BSTG = BK * PB;          // 4224 floats / stage
constexpr int SMEM_CONV = (3 * ASTG + 3 * BSTG) * 4;  // 105984 B

__global__ __launch_bounds__(256, 2) void conv_gemm(GemmBatch batch) {
    const GemmDesc gd = batch.g[blockIdx.z];
    extern __shared__ float smem[];
    float* As = smem;
    float* Bs = smem + 3 * ASTG;

    const int tid  = threadIdx.x;
    const int lane = tid & 31;
    const int warp = tid >> 5;
    const int gq   = lane >> 2;
    const int tg   = lane & 3;
    const int wm   = (warp >> 2) * 64;
    const int wn   = (warp & 3) * 32;
    const int bm0  = blockIdx.x * 128;
    const int bn0  = blockIdx.y * 128;

    float acc[4][4][4];
#pragma unroll
    for (int mi = 0; mi < 4; mi++)
#pragma unroll
        for (int ni = 0; ni < 4; ni++)
#pragma unroll
            for (int r = 0; r < 4; r++) acc[mi][ni][r] = 0.f;

    // stage loader
    auto load_stage = [&](int stg, int k0) {
        float* A = As + stg * ASTG;
        float* B = Bs + stg * BSTG;
#pragma unroll
        for (int j = 0; j < 4; j++) {              // A: 1024 chunks of 16B
            int idx = tid + j * 256;
            int r = idx >> 3, c4 = idx & 7;
            cp16(A + r * PA + c4 * 4, gd.W + (size_t)(bm0 + r) * DMODEL + k0 + c4 * 4);
        }
#pragma unroll
        for (int j = 0; j < 4; j++) {              // B: 1024 chunks of 16B
            int idx = tid + j * 256;
            int r = idx >> 5, c = idx & 31;
            cp16(B + r * PB + c * 4, gd.X + (size_t)(k0 + r) * NSEQ + bn0 + c * 4);
        }
    };

    load_stage(0, 0);
    CP_COMMIT();

#pragma unroll 1
    for (int i = 0; i < 32; i++) {
        if (i < 31) load_stage((i + 1) % 3, (i + 1) * BK);
        CP_COMMIT();
        CP_WAIT1();
        __syncthreads();

        const float* A = As + (i % 3) * ASTG;
        const float* B = Bs + (i % 3) * BSTG;
#pragma unroll
        for (int kk = 0; kk < BK; kk += 8) {
            uint32_t af[4][4], bf[4][2];
#pragma unroll
            for (int mi = 0; mi < 4; mi++) {
                int base = (wm + mi * 16 + gq) * PA + kk + tg;
                af[mi][0] = __float_as_uint(A[base]);
                af[mi][1] = __float_as_uint(A[base + 8 * PA]);
                af[mi][2] = __float_as_uint(A[base + 4]);
                af[mi][3] = __float_as_uint(A[base + 8 * PA + 4]);
            }
#pragma unroll
            for (int ni = 0; ni < 4; ni++) {
                int col = wn + ni * 8 + gq;
                bf[ni][0] = __float_as_uint(B[(kk + tg) * PB + col]);
                bf[ni][1] = __float_as_uint(B[(kk + tg + 4) * PB + col]);
            }
#pragma unroll
            for (int mi = 0; mi < 4; mi++)
#pragma unroll
                for (int ni = 0; ni < 4; ni++)
                    mma_tf32(acc[mi][ni], af[mi], bf[ni][0], bf[ni][1]);
        }
    }

    // epilogue: bias + optional residual (+ tf32 mirror for downstream GEMMs)
#pragma unroll
    for (int mi = 0; mi < 4; mi++) {
        int row0 = bm0 + wm + mi * 16 + gq;
        int row1 = row0 + 8;
        float b0 = gd.bias[row0], b1 = gd.bias[row1];
#pragma unroll
        for (int ni = 0; ni < 4; ni++) {
            int col = bn0 + wn + ni * 8 + tg * 2;
            size_t i0 = (size_t)row0 * NSEQ + col;
            size_t i1 = (size_t)row1 * NSEQ + col;
            float v00 = acc[mi][ni][0] + b0, v01 = acc[mi][ni][1] + b0;
            float v10 = acc[mi][ni][2] + b1, v11 = acc[mi][ni][3] + b1;
            if (gd.R) {
                v00 += gd.R[i0]; v01 += gd.R[i0 + 1];
                v10 += gd.R[i1]; v11 += gd.R[i1 + 1];
            }
            gd.Y[i0] = v00; gd.Y[i0 + 1] = v01;
            gd.Y[i1] = v10; gd.Y[i1 + 1] = v11;
            if (gd.Ytf) {
                gd.Ytf[i0]     = __uint_as_float(f2tf32(v00));
                gd.Ytf[i0 + 1] = __uint_as_float(f2tf32(v01));
                gd.Ytf[i1]     = __uint_as_float(f2tf32(v10));
                gd.Ytf[i1 + 1] = __uint_as_float(f2tf32(v11));
            }
        }
    }
}

// ---------------- tensor-core flash attention over d-slices ----------------
// Per d-slice: S[n,m] = (1/8) sum_h Q[d16+h,n] K[d16+h,m]; P=softmax_m(S);
// X[d16+h,n] = sum_m V[d16+h,m] P[n,m].  exp without max-sub (scores tiny).
// CTA: 256 threads = 8 warps, one (item, d, 256-row n-block). Warp: 32 rows.
// K,V staged in smem as tf32 bits, layout [h][ m ^ ((h&3)<<3) ] (conflict-free).

#define QSCALE (0.125f * 1.4426950408889634f)   // 1/sqrt(64) * log2(e)

__global__ __launch_bounds__(256) void flash_kernel(const float* __restrict__ Qb,
                                                    const float* __restrict__ Kb,
                                                    const float* __restrict__ Vb,
                                                    float* __restrict__ Xb) {
    extern __shared__ uint32_t fsm[];
    uint32_t* Ks = fsm;                  // [16][1024] tf32 bits, swizzled
    uint32_t* Vs = fsm + 16 * NSEQ;

    const int item = blockIdx.z;
    const int d    = blockIdx.x;
    const int nb   = blockIdx.y * 256;
    const int tid  = threadIdx.x;
    const int warp = tid >> 5;
    const int lane = tid & 31;
    const int gq   = lane >> 2;
    const int tg   = lane & 3;

    const float* Qg = Qb + (size_t)item * MN + (size_t)(d * 16) * NSEQ;
    const float* Kg = Kb + (size_t)item * MN + (size_t)(d * 16) * NSEQ;
    const float* Vg = Vb + (size_t)item * MN + (size_t)(d * 16) * NSEQ;
    float*       Xg = Xb + (size_t)item * MN + (size_t)(d * 16) * NSEQ;

    // ---- fill K/V smem with tf32 conversion + XOR swizzle
    const float4* K4 = (const float4*)Kg;
    const float4* V4 = (const float4*)Vg;
#pragma unroll
    for (int j = 0; j < 16; j++) {
        int idx = tid + j * 256;          // 4096 float4s
        int h = idx >> 8;
        int m = (idx & 255) * 4;
        int c = m ^ ((h & 3) << 3);
        float4 kv = K4[idx];
        uint4 u;
        u.x = f2tf32(kv.x); u.y = f2tf32(kv.y); u.z = f2tf32(kv.z); u.w = f2tf32(kv.w);
        *(uint4*)&Ks[h * NSEQ + c] = u;
        float4 vv = V4[idx];
        uint4 w;
        w.x = f2tf32(vv.x); w.y = f2tf32(vv.y); w.z = f2tf32(vv.z); w.w = f2tf32(vv.w);
        *(uint4*)&Vs[h * NSEQ + c] = w;
    }
    __syncthreads();

    // ---- Q fragments (A-frag of m16n8k8, rows = n, cols = h), scale folded
    uint32_t qf[2][2][4];
#pragma unroll
    for (int mt = 0; mt < 2; mt++) {
        int n0 = nb + warp * 32 + mt * 16 + gq;
#pragma unroll
        for (int ks = 0; ks < 2; ks++) {
            int h = ks * 8 + tg;
            qf[mt][ks][0] = f2tf32(Qg[(size_t)h * NSEQ + n0] * QSCALE);
            qf[mt][ks][1] = f2tf32(Qg[(size_t)h * NSEQ + n0 + 8] * QSCALE);
            qf[mt][ks][2] = f2tf32(Qg[(size_t)(h + 4) * NSEQ + n0] * QSCALE);
            qf[mt][ks][3] = f2tf32(Qg[(size_t)(h + 4) * NSEQ + n0 + 8] * QSCALE);
        }
    }

    float xacc[2][2][4];
#pragma unroll
    for (int mt = 0; mt < 2; mt++)
#pragma unroll
        for (int ht = 0; ht < 2; ht++)
#pragma unroll
            for (int r = 0; r < 4; r++) xacc[mt][ht][r] = 0.f;
    float l[4] = {0.f, 0.f, 0.f, 0.f};

#pragma unroll 2
    for (int m0 = 0; m0 < NSEQ; m0 += 8) {
        // K B-fragments (k = h)
        int cm = (m0 + gq) ^ (tg << 3);
        uint32_t kf0 = Ks[tg * NSEQ + cm];
        uint32_t kf1 = Ks[(tg + 4) * NSEQ + cm];
        uint32_t kf2 = Ks[(tg + 8) * NSEQ + cm];
        uint32_t kf3 = Ks[(tg + 12) * NSEQ + cm];

        // V B-fragments with permuted k (k=tg -> m0+2tg, k=tg+4 -> m0+2tg+1)
        int cv = (m0 + 2 * tg) ^ ((gq & 3) << 3);
        uint2 vf0 = *(const uint2*)&Vs[gq * NSEQ + cv];
        uint2 vf1 = *(const uint2*)&Vs[(8 + gq) * NSEQ + cv];

#pragma unroll
        for (int mt = 0; mt < 2; mt++) {
            float s[4] = {0.f, 0.f, 0.f, 0.f};
            mma_tf32(s, qf[mt][0], kf0, kf1);
            mma_tf32(s, qf[mt][1], kf2, kf3);

            float p0 = ex2f(s[0]), p1 = ex2f(s[1]), p2 = ex2f(s[2]), p3 = ex2f(s[3]);
            l[mt * 2 + 0] += p0 + p1;
            l[mt * 2 + 1] += p2 + p3;

            // C-frag -> A-frag of PV via permuted k:
            // a0=(gq,k=tg)->p(c0)  a1=(gq+8,tg)->p(c2)  a2=(gq,tg+4)->p(c1)  a3->p(c3)
            uint32_t pa[4];
            pa[0] = f2tf32(p0); pa[1] = f2tf32(p2); pa[2] = f2tf32(p1); pa[3] = f2tf32(p3);

            mma_tf32(xacc[mt][0], pa, vf0.x, vf0.y);
            mma_tf32(xacc[mt][1], pa, vf1.x, vf1.y);
        }
    }

    // ---- row-sum reduce across the 4-lane group, normalize, store (tf32-clean)
#pragma unroll
    for (int i = 0; i < 4; i++) {
        l[i] += __shfl_xor_sync(0xffffffffu, l[i], 1);
        l[i] += __shfl_xor_sync(0xffffffffu, l[i], 2);
    }
#pragma unroll
    for (int mt = 0; mt < 2; mt++) {
        float inv0 = 1.0f / l[mt * 2 + 0];
        float inv1 = 1.0f / l[mt * 2 + 1];
        int n0 = nb + warp * 32 + mt * 16 + gq;
#pragma unroll
        for (int ht = 0; ht < 2; ht++) {
            int h = ht * 8 + 2 * tg;
            Xg[(size_t)h * NSEQ + n0]           = __uint_as_float(f2tf32(xacc[mt][ht][0] * inv0));
            Xg[(size_t)(h + 1) * NSEQ + n0]     = __uint_as_float(f2tf32(xacc[mt][ht][1] * inv0));
            Xg[(size_t)h * NSEQ + n0 + 8]       = __uint_as_float(f2tf32(xacc[mt][ht][2] * inv1));
            Xg[(size_t)(h + 1) * NSEQ + n0 + 8] = __uint_as_float(f2tf32(xacc[mt][ht][3] * inv1));
        }
    }
}

// ---------------- launch ----------------
extern "C" void kernel_launch(void* const* d_in, const int* in_sizes, int n_in,
                              void* d_out, int out_size) {
    (void)in_sizes; (void)n_in; (void)out_size;

    const float* desc0 = (const float*)d_in[0];
    const float* desc1 = (const float*)d_in[1];
    const float* Wq = (const float*)d_in[2]; const float* bq = (const float*)d_in[3];
    const float* Wk = (const float*)d_in[4]; const float* bk = (const float*)d_in[5];
    const float* Wv = (const float*)d_in[6]; const float* bv = (const float*)d_in[7];
    const float* Wm = (const float*)d_in[8]; const float* bm = (const float*)d_in[9];

    float* out0 = (float*)d_out;
    float* out1 = out0 + MN;

    float *Qb, *Kb, *Vb, *Xb, *Wt, *Dt, *Tt;
    cudaGetSymbolAddress((void**)&Qb, g_Q);
    cudaGetSymbolAddress((void**)&Kb, g_K);
    cudaGetSymbolAddress((void**)&Vb, g_V);
    cudaGetSymbolAddress((void**)&Xb, g_X);
    cudaGetSymbolAddress((void**)&Wt, g_W);
    cudaGetSymbolAddress((void**)&Dt, g_D);
    cudaGetSymbolAddress((void**)&Tt, g_T);

    float* W0 = Wt;           // Wq'
    float* W1 = Wt + MN;      // Wk'
    float* W2 = Wt + 2 * MN;  // Wv'
    float* W3 = Wt + 3 * MN;  // Wm'
    float* D0 = Dt;           // desc0'
    float* D1 = Dt + MN;      // desc1'
    float* T0 = Tt;           // out0' (tf32 mirror)
    float* T1 = Tt + MN;      // out1'

    cudaFuncSetAttribute(conv_gemm, cudaFuncAttributeMaxDynamicSharedMemorySize, SMEM_CONV);
    cudaFuncSetAttribute(flash_kernel, cudaFuncAttributeMaxDynamicSharedMemorySize, 131072);

    // ---- prep: tf32-round the 4 weights and both descs
    CvtBatch cb{};
    cb.s[0] = Wq; cb.d[0] = W0;
    cb.s[1] = Wk; cb.d[1] = W1;
    cb.s[2] = Wv; cb.d[2] = W2;
    cb.s[3] = Wm; cb.d[3] = W3;
    cb.s[4] = desc0; cb.d[4] = D0;
    cb.s[5] = desc1; cb.d[5] = D1;
    prep_kernel<<<dim3(1024, 6), 256>>>(cb);

    // ---- attn1 (desc0 self) + attn2 (desc1 self): QKV GEMMs
    GemmBatch A{};
    A.g[0] = {W0, bq, D0, nullptr, Qb, nullptr};
    A.g[1] = {W1, bk, D0, nullptr, Kb, nullptr};
    A.g[2] = {W2, bv, D0, nullptr, Vb, nullptr};
    A.g[3] = {W0, bq, D1, nullptr, Qb + MN, nullptr};
    A.g[4] = {W1, bk, D1, nullptr, Kb + MN, nullptr};
    A.g[5] = {W2, bv, D1, nullptr, Vb + MN, nullptr};
    conv_gemm<<<dim3(8, 8, 6), 256, SMEM_CONV>>>(A);

    flash_kernel<<<dim3(64, 4, 2), 256, 131072>>>(Qb, Kb, Vb, Xb);

    // d0 = desc0 + Wm@X0 + bm ; d1 = desc1 + Wm@X1 + bm
    GemmBatch C{};
    C.g[0] = {W3, bm, Xb,      desc0, out0, T0};
    C.g[1] = {W3, bm, Xb + MN, desc1, out1, T1};
    conv_gemm<<<dim3(8, 8, 2), 256, SMEM_CONV>>>(C);

    // ---- attn3: q=d0, kv=d1
    GemmBatch Dq{};
    Dq.g[0] = {W0, bq, T0, nullptr, Qb, nullptr};
    Dq.g[1] = {W1, bk, T1, nullptr, Kb, nullptr};
    Dq.g[2] = {W2, bv, T1, nullptr, Vb, nullptr};
    conv_gemm<<<dim3(8, 8, 3), 256, SMEM_CONV>>>(Dq);

    flash_kernel<<<dim3(64, 4, 1), 256, 131072>>>(Qb, Kb, Vb, Xb);

    GemmBatch F{};
    F.g[0] = {W3, bm, Xb, out0, out0, T0};   // d0 += conv(x); refresh T0
    conv_gemm<<<dim3(8, 8, 1), 256, SMEM_CONV>>>(F);

    // ---- attn4: q=d1 (pre-update), kv=d0 (updated)
    GemmBatch G{};
    G.g[0] = {W0, bq, T1, nullptr, Qb, nullptr};
    G.g[1] = {W1, bk, T0, nullptr, Kb, nullptr};
    G.g[2] = {W2, bv, T0, nullptr, Vb, nullptr};
    conv_gemm<<<dim3(8, 8, 3), 256, SMEM_CONV>>>(G);

    flash_kernel<<<dim3(64, 4, 1), 256, 131072>>>(Qb, Kb, Vb, Xb);

    GemmBatch I{};
    I.g[0] = {W3, bm, Xb, out1, out1, nullptr};   // d1 += conv(x), final
    conv_gemm<<<dim3(8, 8, 1), 256, SMEM_CONV>>>(I);
}

// round 5
// speedup vs baseline: 2.0819x; 1.0704x over previous
#include <cuda_runtime.h>
#include <cstdint>

#define DMODEL 1024
#define NSEQ   1024
static const int MN = DMODEL * NSEQ;

// ---------------- scratch (device globals; no allocs allowed) ----------------
__device__ float g_Q[2 * 1024 * 1024];
__device__ float g_K[2 * 1024 * 1024];
__device__ float g_V[2 * 1024 * 1024];
__device__ float g_X[2 * 1024 * 1024];
__device__ float g_W[4 * 1024 * 1024];   // tf32-rounded weights
__device__ float g_D[2 * 1024 * 1024];   // tf32-rounded desc0/desc1
__device__ float g_T[2 * 1024 * 1024];   // tf32-rounded copies of out0/out1

__device__ __forceinline__ uint32_t f2tf32(float f) {
    uint32_t r;
    asm("cvt.rna.tf32.f32 %0, %1;" : "=r"(r) : "f"(f));
    return r;
}
__device__ __forceinline__ float ex2f(float x) {
    float y;
    asm("ex2.approx.f32 %0, %1;" : "=f"(y) : "f"(x));
    return y;
}
__device__ __forceinline__ void mma_tf32(float* d, const uint32_t* a, uint32_t b0, uint32_t b1) {
    asm volatile(
        "mma.sync.aligned.m16n8k8.row.col.f32.tf32.tf32.f32 "
        "{%0,%1,%2,%3}, {%4,%5,%6,%7}, {%8,%9}, {%0,%1,%2,%3};"
        : "+f"(d[0]), "+f"(d[1]), "+f"(d[2]), "+f"(d[3])
        : "r"(a[0]), "r"(a[1]), "r"(a[2]), "r"(a[3]), "r"(b0), "r"(b1));
}
__device__ __forceinline__ void cp16(void* dst, const void* src) {
    uint32_t d = (uint32_t)__cvta_generic_to_shared(dst);
    asm volatile("cp.async.cg.shared.global [%0], [%1], 16;" :: "r"(d), "l"(src));
}
#define CP_COMMIT() asm volatile("cp.async.commit_group;")
#define CP_WAIT1()  asm volatile("cp.async.wait_group 1;")

// ---------------- prep: tf32-round W matrices and descs ----------------
struct CvtBatch { const float* s[6]; float* d[6]; };

__global__ __launch_bounds__(256) void prep_kernel(CvtBatch cb) {
    const float4* s = (const float4*)cb.s[blockIdx.y];
    uint4*        d = (uint4*)cb.d[blockIdx.y];
    int i = blockIdx.x * 256 + threadIdx.x;
    float4 v = s[i];
    uint4 u;
    u.x = f2tf32(v.x); u.y = f2tf32(v.y); u.z = f2tf32(v.z); u.w = f2tf32(v.w);
    d[i] = u;
}

// ---------------- tf32 GEMM, 2-stage cp.async pipeline, 2 CTAs/SM ------------
// Y = W @ X + bias (+ R). W,X PRE-ROUNDED to tf32 grid (no cvt in loop).
// W: [1024,1024] row-major (m,k) ; X: [1024,1024] row-major (k,n)

struct GemmDesc { const float *W, *bias, *X, *R; float *Y, *Ytf; };
struct GemmBatch { GemmDesc g[6]; };

constexpr int BK = 32;
constexpr int PA = 36;                 // A smem pitch (floats): [m][k]
constexpr int PB = 136;                // B smem pitch (floats): [k][n]  (8 mod 32 -> conflict-free)
constexpr int ASTG = 128 * PA;         // 4608 floats / stage
constexpr int BSTG = BK * PB;          // 4352 floats / stage
constexpr int SMEM_CONV = 2 * (ASTG + BSTG) * 4;   // 71680 B

__global__ __launch_bounds__(256, 2) void conv_gemm(GemmBatch batch) {
    const GemmDesc gd = batch.g[blockIdx.z];
    extern __shared__ float smem[];
    float* As = smem;
    float* Bs = smem + 2 * ASTG;

    const int tid  = threadIdx.x;
    const int lane = tid & 31;
    const int warp = tid >> 5;
    const int gq   = lane >> 2;
    const int tg   = lane & 3;
    const int wm   = (warp >> 2) * 64;
    const int wn   = (warp & 3) * 32;
    const int bm0  = blockIdx.x * 128;
    const int bn0  = blockIdx.y * 128;

    float acc[4][4][4];
#pragma unroll
    for (int mi = 0; mi < 4; mi++)
#pragma unroll
        for (int ni = 0; ni < 4; ni++)
#pragma unroll
            for (int r = 0; r < 4; r++) acc[mi][ni][r] = 0.f;

    auto load_stage = [&](int stg, int k0) {
        float* A = As + stg * ASTG;
        float* B = Bs + stg * BSTG;
#pragma unroll
        for (int j = 0; j < 4; j++) {              // A tile: 1024 x 16B
            int idx = tid + j * 256;
            int r = idx >> 3, c4 = idx & 7;
            cp16(A + r * PA + c4 * 4, gd.W + (size_t)(bm0 + r) * DMODEL + k0 + c4 * 4);
        }
#pragma unroll
        for (int j = 0; j < 4; j++) {              // B tile: 1024 x 16B
            int idx = tid + j * 256;
            int r = idx >> 5, c = idx & 31;
            cp16(B + r * PB + c * 4, gd.X + (size_t)(k0 + r) * NSEQ + bn0 + c * 4);
        }
    };

    load_stage(0, 0);  CP_COMMIT();
    load_stage(1, 32); CP_COMMIT();

#pragma unroll 1
    for (int i = 0; i < 32; i++) {
        const int s = i & 1;
        CP_WAIT1();                 // stage i resident (groups complete in order)
        __syncthreads();

        const float* A = As + s * ASTG;
        const float* B = Bs + s * BSTG;
#pragma unroll
        for (int kk = 0; kk < BK; kk += 8) {
            uint32_t af[4][4], bf[4][2];
#pragma unroll
            for (int mi = 0; mi < 4; mi++) {
                int base = (wm + mi * 16 + gq) * PA + kk + tg;
                af[mi][0] = __float_as_uint(A[base]);
                af[mi][1] = __float_as_uint(A[base + 8 * PA]);
                af[mi][2] = __float_as_uint(A[base + 4]);
                af[mi][3] = __float_as_uint(A[base + 8 * PA + 4]);
            }
#pragma unroll
            for (int ni = 0; ni < 4; ni++) {
                int col = wn + ni * 8 + gq;
                bf[ni][0] = __float_as_uint(B[(kk + tg) * PB + col]);
                bf[ni][1] = __float_as_uint(B[(kk + tg + 4) * PB + col]);
            }
#pragma unroll
            for (int mi = 0; mi < 4; mi++)
#pragma unroll
                for (int ni = 0; ni < 4; ni++)
                    mma_tf32(acc[mi][ni], af[mi], bf[ni][0], bf[ni][1]);
        }
        __syncthreads();            // all warps done reading stage s
        if (i < 30) load_stage(s, (i + 2) * BK);
        CP_COMMIT();                // commit every iter (empty groups keep counts aligned)
    }

    // epilogue: bias + optional residual (+ tf32 mirror for downstream GEMMs)
#pragma unroll
    for (int mi = 0; mi < 4; mi++) {
        int row0 = bm0 + wm + mi * 16 + gq;
        int row1 = row0 + 8;
        float b0 = gd.bias[row0], b1 = gd.bias[row1];
#pragma unroll
        for (int ni = 0; ni < 4; ni++) {
            int col = bn0 + wn + ni * 8 + tg * 2;
            size_t i0 = (size_t)row0 * NSEQ + col;
            size_t i1 = (size_t)row1 * NSEQ + col;
            float v00 = acc[mi][ni][0] + b0, v01 = acc[mi][ni][1] + b0;
            float v10 = acc[mi][ni][2] + b1, v11 = acc[mi][ni][3] + b1;
            if (gd.R) {
                v00 += gd.R[i0]; v01 += gd.R[i0 + 1];
                v10 += gd.R[i1]; v11 += gd.R[i1 + 1];
            }
            gd.Y[i0] = v00; gd.Y[i0 + 1] = v01;
            gd.Y[i1] = v10; gd.Y[i1 + 1] = v11;
            if (gd.Ytf) {
                gd.Ytf[i0]     = __uint_as_float(f2tf32(v00));
                gd.Ytf[i0 + 1] = __uint_as_float(f2tf32(v01));
                gd.Ytf[i1]     = __uint_as_float(f2tf32(v10));
                gd.Ytf[i1 + 1] = __uint_as_float(f2tf32(v11));
            }
        }
    }
}

// ---------------- tensor-core flash attention over d-slices ----------------
#define QSCALE (0.125f * 1.4426950408889634f)   // 1/sqrt(64) * log2(e)

__global__ __launch_bounds__(256) void flash_kernel(const float* __restrict__ Qb,
                                                    const float* __restrict__ Kb,
                                                    const float* __restrict__ Vb,
                                                    float* __restrict__ Xb) {
    extern __shared__ uint32_t fsm[];
    uint32_t* Ks = fsm;                  // [16][1024] tf32 bits, swizzled
    uint32_t* Vs = fsm + 16 * NSEQ;

    const int item = blockIdx.z;
    const int d    = blockIdx.x;
    const int nb   = blockIdx.y * 256;
    const int tid  = threadIdx.x;
    const int warp = tid >> 5;
    const int lane = tid & 31;
    const int gq   = lane >> 2;
    const int tg   = lane & 3;

    const float* Qg = Qb + (size_t)item * MN + (size_t)(d * 16) * NSEQ;
    const float* Kg = Kb + (size_t)item * MN + (size_t)(d * 16) * NSEQ;
    const float* Vg = Vb + (size_t)item * MN + (size_t)(d * 16) * NSEQ;
    float*       Xg = Xb + (size_t)item * MN + (size_t)(d * 16) * NSEQ;

    const float4* K4 = (const float4*)Kg;
    const float4* V4 = (const float4*)Vg;
#pragma unroll
    for (int j = 0; j < 16; j++) {
        int idx = tid + j * 256;          // 4096 float4s
        int h = idx >> 8;
        int m = (idx & 255) * 4;
        int c = m ^ ((h & 3) << 3);
        float4 kv = K4[idx];
        uint4 u;
        u.x = f2tf32(kv.x); u.y = f2tf32(kv.y); u.z = f2tf32(kv.z); u.w = f2tf32(kv.w);
        *(uint4*)&Ks[h * NSEQ + c] = u;
        float4 vv = V4[idx];
        uint4 w;
        w.x = f2tf32(vv.x); w.y = f2tf32(vv.y); w.z = f2tf32(vv.z); w.w = f2tf32(vv.w);
        *(uint4*)&Vs[h * NSEQ + c] = w;
    }
    __syncthreads();

    uint32_t qf[2][2][4];
#pragma unroll
    for (int mt = 0; mt < 2; mt++) {
        int n0 = nb + warp * 32 + mt * 16 + gq;
#pragma unroll
        for (int ks = 0; ks < 2; ks++) {
            int h = ks * 8 + tg;
            qf[mt][ks][0] = f2tf32(Qg[(size_t)h * NSEQ + n0] * QSCALE);
            qf[mt][ks][1] = f2tf32(Qg[(size_t)h * NSEQ + n0 + 8] * QSCALE);
            qf[mt][ks][2] = f2tf32(Qg[(size_t)(h + 4) * NSEQ + n0] * QSCALE);
            qf[mt][ks][3] = f2tf32(Qg[(size_t)(h + 4) * NSEQ + n0 + 8] * QSCALE);
        }
    }

    float xacc[2][2][4];
#pragma unroll
    for (int mt = 0; mt < 2; mt++)
#pragma unroll
        for (int ht = 0; ht < 2; ht++)
#pragma unroll
            for (int r = 0; r < 4; r++) xacc[mt][ht][r] = 0.f;
    float l[4] = {0.f, 0.f, 0.f, 0.f};

#pragma unroll 2
    for (int m0 = 0; m0 < NSEQ; m0 += 8) {
        int cm = (m0 + gq) ^ (tg << 3);
        uint32_t kf0 = Ks[tg * NSEQ + cm];
        uint32_t kf1 = Ks[(tg + 4) * NSEQ + cm];
        uint32_t kf2 = Ks[(tg + 8) * NSEQ + cm];
        uint32_t kf3 = Ks[(tg + 12) * NSEQ + cm];

        int cv = (m0 + 2 * tg) ^ ((gq & 3) << 3);
        uint2 vf0 = *(const uint2*)&Vs[gq * NSEQ + cv];
        uint2 vf1 = *(const uint2*)&Vs[(8 + gq) * NSEQ + cv];

#pragma unroll
        for (int mt = 0; mt < 2; mt++) {
            float s[4] = {0.f, 0.f, 0.f, 0.f};
            mma_tf32(s, qf[mt][0], kf0, kf1);
            mma_tf32(s, qf[mt][1], kf2, kf3);

            float p0 = ex2f(s[0]), p1 = ex2f(s[1]), p2 = ex2f(s[2]), p3 = ex2f(s[3]);
            l[mt * 2 + 0] += p0 + p1;
            l[mt * 2 + 1] += p2 + p3;

            uint32_t pa[4];
            pa[0] = f2tf32(p0); pa[1] = f2tf32(p2); pa[2] = f2tf32(p1); pa[3] = f2tf32(p3);

            mma_tf32(xacc[mt][0], pa, vf0.x, vf0.y);
            mma_tf32(xacc[mt][1], pa, vf1.x, vf1.y);
        }
    }

#pragma unroll
    for (int i = 0; i < 4; i++) {
        l[i] += __shfl_xor_sync(0xffffffffu, l[i], 1);
        l[i] += __shfl_xor_sync(0xffffffffu, l[i], 2);
    }
#pragma unroll
    for (int mt = 0; mt < 2; mt++) {
        float inv0 = 1.0f / l[mt * 2 + 0];
        float inv1 = 1.0f / l[mt * 2 + 1];
        int n0 = nb + warp * 32 + mt * 16 + gq;
#pragma unroll
        for (int ht = 0; ht < 2; ht++) {
            int h = ht * 8 + 2 * tg;
            Xg[(size_t)h * NSEQ + n0]           = __uint_as_float(f2tf32(xacc[mt][ht][0] * inv0));
            Xg[(size_t)(h + 1) * NSEQ + n0]     = __uint_as_float(f2tf32(xacc[mt][ht][1] * inv0));
            Xg[(size_t)h * NSEQ + n0 + 8]       = __uint_as_float(f2tf32(xacc[mt][ht][2] * inv1));
            Xg[(size_t)(h + 1) * NSEQ + n0 + 8] = __uint_as_float(f2tf32(xacc[mt][ht][3] * inv1));
        }
    }
}

// ---------------- launch ----------------
extern "C" void kernel_launch(void* const* d_in, const int* in_sizes, int n_in,
                              void* d_out, int out_size) {
    (void)in_sizes; (void)n_in; (void)out_size;

    const float* desc0 = (const float*)d_in[0];
    const float* desc1 = (const float*)d_in[1];
    const float* Wq = (const float*)d_in[2]; const float* bq = (const float*)d_in[3];
    const float* Wk = (const float*)d_in[4]; const float* bk = (const float*)d_in[5];
    const float* Wv = (const float*)d_in[6]; const float* bv = (const float*)d_in[7];
    const float* Wm = (const float*)d_in[8]; const float* bm = (const float*)d_in[9];

    float* out0 = (float*)d_out;
    float* out1 = out0 + MN;

    float *Qb, *Kb, *Vb, *Xb, *Wt, *Dt, *Tt;
    cudaGetSymbolAddress((void**)&Qb, g_Q);
    cudaGetSymbolAddress((void**)&Kb, g_K);
    cudaGetSymbolAddress((void**)&Vb, g_V);
    cudaGetSymbolAddress((void**)&Xb, g_X);
    cudaGetSymbolAddress((void**)&Wt, g_W);
    cudaGetSymbolAddress((void**)&Dt, g_D);
    cudaGetSymbolAddress((void**)&Tt, g_T);

    float* W0 = Wt;           float* W1 = Wt + MN;
    float* W2 = Wt + 2 * MN;  float* W3 = Wt + 3 * MN;
    float* D0 = Dt;           float* D1 = Dt + MN;
    float* T0 = Tt;           float* T1 = Tt + MN;

    cudaFuncSetAttribute(conv_gemm, cudaFuncAttributeMaxDynamicSharedMemorySize, SMEM_CONV);
    cudaFuncSetAttribute(conv_gemm, cudaFuncAttributePreferredSharedMemoryCarveout,
                         cudaSharedmemCarveoutMaxShared);
    cudaFuncSetAttribute(flash_kernel, cudaFuncAttributeMaxDynamicSharedMemorySize, 131072);

    // ---- prep: tf32-round the 4 weights and both descs
    CvtBatch cb{};
    cb.s[0] = Wq; cb.d[0] = W0;
    cb.s[1] = Wk; cb.d[1] = W1;
    cb.s[2] = Wv; cb.d[2] = W2;
    cb.s[3] = Wm; cb.d[3] = W3;
    cb.s[4] = desc0; cb.d[4] = D0;
    cb.s[5] = desc1; cb.d[5] = D1;
    prep_kernel<<<dim3(1024, 6), 256>>>(cb);

    // ---- attn1 (desc0 self) + attn2 (desc1 self): QKV GEMMs
    GemmBatch A{};
    A.g[0] = {W0, bq, D0, nullptr, Qb, nullptr};
    A.g[1] = {W1, bk, D0, nullptr, Kb, nullptr};
    A.g[2] = {W2, bv, D0, nullptr, Vb, nullptr};
    A.g[3] = {W0, bq, D1, nullptr, Qb + MN, nullptr};
    A.g[4] = {W1, bk, D1, nullptr, Kb + MN, nullptr};
    A.g[5] = {W2, bv, D1, nullptr, Vb + MN, nullptr};
    conv_gemm<<<dim3(8, 8, 6), 256, SMEM_CONV>>>(A);

    flash_kernel<<<dim3(64, 4, 2), 256, 131072>>>(Qb, Kb, Vb, Xb);

    // d0 = desc0 + Wm@X0 + bm ; d1 = desc1 + Wm@X1 + bm
    GemmBatch C{};
    C.g[0] = {W3, bm, Xb,      desc0, out0, T0};
    C.g[1] = {W3, bm, Xb + MN, desc1, out1, T1};
    conv_gemm<<<dim3(8, 8, 2), 256, SMEM_CONV>>>(C);

    // ---- attn3: q=d0, kv=d1
    GemmBatch Dq{};
    Dq.g[0] = {W0, bq, T0, nullptr, Qb, nullptr};
    Dq.g[1] = {W1, bk, T1, nullptr, Kb, nullptr};
    Dq.g[2] = {W2, bv, T1, nullptr, Vb, nullptr};
    conv_gemm<<<dim3(8, 8, 3), 256, SMEM_CONV>>>(Dq);

    flash_kernel<<<dim3(64, 4, 1), 256, 131072>>>(Qb, Kb, Vb, Xb);

    // ---- F (d0 += conv(x), refresh T0) merged with attn4's Q GEMM (needs only T1)
    GemmBatch FG{};
    FG.g[0] = {W3, bm, Xb, out0, out0, T0};
    FG.g[1] = {W0, bq, T1, nullptr, Qb, nullptr};
    conv_gemm<<<dim3(8, 8, 2), 256, SMEM_CONV>>>(FG);

    // ---- attn4 K,V GEMMs (need T0 from F)
    GemmBatch G{};
    G.g[0] = {W1, bk, T0, nullptr, Kb, nullptr};
    G.g[1] = {W2, bv, T0, nullptr, Vb, nullptr};
    conv_gemm<<<dim3(8, 8, 2), 256, SMEM_CONV>>>(G);

    flash_kernel<<<dim3(64, 4, 1), 256, 131072>>>(Qb, Kb, Vb, Xb);

    GemmBatch I{};
    I.g[0] = {W3, bm, Xb, out1, out1, nullptr};
    conv_gemm<<<dim3(8, 8, 1), 256, SMEM_CONV>>>(I);
}

// round 6
// speedup vs baseline: 2.1417x; 1.0287x over previous
#include <cuda_runtime.h>
#include <cstdint>

#define DMODEL 1024
#define NSEQ   1024
static const int MN = DMODEL * NSEQ;

// ---------------- scratch (device globals; no allocs allowed) ----------------
__device__ float g_Q[2 * 1024 * 1024];
__device__ float g_K[2 * 1024 * 1024];
__device__ float g_V[2 * 1024 * 1024];
__device__ float g_X[2 * 1024 * 1024];   // X^T per item: [n][c], tf32-clean
__device__ float g_W[4 * 1024 * 1024];   // tf32-rounded weights [m][k]
__device__ float g_D[2 * 1024 * 1024];   // desc0^T/desc1^T tf32-rounded [n][c]
__device__ float g_T[2 * 1024 * 1024];   // out0^T/out1^T tf32 mirrors [n][c]

__device__ __forceinline__ uint32_t f2tf32(float f) {
    uint32_t r;
    asm("cvt.rna.tf32.f32 %0, %1;" : "=r"(r) : "f"(f));
    return r;
}
__device__ __forceinline__ float ex2f(float x) {
    float y;
    asm("ex2.approx.f32 %0, %1;" : "=f"(y) : "f"(x));
    return y;
}
__device__ __forceinline__ void mma_tf32(float* d, const uint32_t* a, uint32_t b0, uint32_t b1) {
    asm volatile(
        "mma.sync.aligned.m16n8k8.row.col.f32.tf32.tf32.f32 "
        "{%0,%1,%2,%3}, {%4,%5,%6,%7}, {%8,%9}, {%0,%1,%2,%3};"
        : "+f"(d[0]), "+f"(d[1]), "+f"(d[2]), "+f"(d[3])
        : "r"(a[0]), "r"(a[1]), "r"(a[2]), "r"(a[3]), "r"(b0), "r"(b1));
}
__device__ __forceinline__ void ldsm4(uint32_t& r0, uint32_t& r1, uint32_t& r2, uint32_t& r3,
                                      uint32_t addr) {
    asm volatile("ldmatrix.sync.aligned.m8n8.x4.shared.b16 {%0,%1,%2,%3}, [%4];"
                 : "=r"(r0), "=r"(r1), "=r"(r2), "=r"(r3) : "r"(addr));
}
__device__ __forceinline__ void cp16(uint32_t dst, const void* src) {
    asm volatile("cp.async.cg.shared.global [%0], [%1], 16;" :: "r"(dst), "l"(src));
}
#define CP_COMMIT() asm volatile("cp.async.commit_group;")
#define CP_WAIT1()  asm volatile("cp.async.wait_group 1;")

// ---------------- prep: tf32-round weights; transpose+round descs ------------
struct CvtBatch { const float* s[4]; float* d[4]; };

__global__ __launch_bounds__(256) void prep_round(CvtBatch cb) {
    const float4* s = (const float4*)cb.s[blockIdx.y];
    uint4*        d = (uint4*)cb.d[blockIdx.y];
    int i = blockIdx.x * 256 + threadIdx.x;
    float4 v = s[i];
    uint4 u;
    u.x = f2tf32(v.x); u.y = f2tf32(v.y); u.z = f2tf32(v.z); u.w = f2tf32(v.w);
    d[i] = u;
}

struct CvtTBatch { const float* s[2]; float* d[2]; };

// dst[n][c] = tf32(src[c][n])
__global__ __launch_bounds__(256) void prep_round_T(CvtTBatch cb) {
    __shared__ float t[32][33];
    const float* src = cb.s[blockIdx.z];
    float*       dst = cb.d[blockIdx.z];
    int tx = threadIdx.x & 31, ty = threadIdx.x >> 5;
    int cb0 = blockIdx.y * 32, nb0 = blockIdx.x * 32;
#pragma unroll
    for (int j = 0; j < 4; j++)
        t[ty + j * 8][tx] = src[(size_t)(cb0 + ty + j * 8) * NSEQ + nb0 + tx];
    __syncthreads();
#pragma unroll
    for (int j = 0; j < 4; j++)
        dst[(size_t)(nb0 + ty + j * 8) * DMODEL + cb0 + tx] =
            __uint_as_float(f2tf32(t[tx][ty + j * 8]));
}

// ---------------- tf32 GEMM: ldmatrix fragments, 3-stage/1-sync pipeline -----
// Y[m,n] = sum_k W[m,k] * Bt[n,k] + bias[m] (+R).  W [m][k], Bt [n][k], both
// pre-rounded tf32 and k-major (16B = 4 consecutive k).
// smem tiles: 128 rows x 128B, chunk swizzle (c ^ (row&7)).

struct GemmDesc { const float *W, *bias, *X, *R; float *Y, *Ytf; };
struct GemmBatch { GemmDesc g[6]; };

constexpr int BK = 32;
constexpr int STG = 32768;                 // A 16KB + B 16KB
constexpr int SMEM_CONV = 3 * STG;         // 98304 B

__global__ __launch_bounds__(256, 2) void conv_gemm(GemmBatch batch) {
    const GemmDesc gd = batch.g[blockIdx.z];
    extern __shared__ char smem[];
    const uint32_t sbase = (uint32_t)__cvta_generic_to_shared(smem);

    const int tid  = threadIdx.x;
    const int lane = tid & 31;
    const int warp = tid >> 5;
    const int gq   = lane >> 2;
    const int tg   = lane & 3;
    const int wm   = (warp >> 2) * 64;
    const int wn   = (warp & 3) * 32;
    const int bm0  = blockIdx.x * 128;
    const int bn0  = blockIdx.y * 128;

    float acc[4][4][4];
#pragma unroll
    for (int mi = 0; mi < 4; mi++)
#pragma unroll
        for (int ni = 0; ni < 4; ni++)
#pragma unroll
            for (int r = 0; r < 4; r++) acc[mi][ni][r] = 0.f;

    // ldmatrix lane geometry
    const int lj = lane >> 3;          // matrix index 0..3
    const int lr = lane & 7;           // row within matrix
    // A: mat j -> row = wm + mi*16 + (j&1)*8 + r ; kchunk += (j>>1)
    uint32_t aoff[4];
#pragma unroll
    for (int mi = 0; mi < 4; mi++)
        aoff[mi] = (uint32_t)(wm + mi * 16 + (lj & 1) * 8 + lr) * 128;
    const int akc = lj >> 1;
    // B: mat j -> row = wn + g*16 + (j>>1)*8 + r ; kchunk += (j&1)
    uint32_t boff[2];
#pragma unroll
    for (int g = 0; g < 2; g++)
        boff[g] = (uint32_t)(wn + g * 16 + (lj >> 1) * 8 + lr) * 128;
    const int bkc = lj & 1;

    auto load_stage = [&](int stg, int k0) {
        uint32_t A = sbase + stg * STG;
        uint32_t B = A + 16384;
#pragma unroll
        for (int j = 0; j < 4; j++) {              // A: 1024 x 16B
            int idx = tid + j * 256;
            int r = idx >> 3, c = idx & 7;
            cp16(A + r * 128 + ((c ^ (r & 7)) << 4),
                 gd.W + (size_t)(bm0 + r) * DMODEL + k0 + c * 4);
        }
#pragma unroll
        for (int j = 0; j < 4; j++) {              // B: 1024 x 16B
            int idx = tid + j * 256;
            int r = idx >> 3, c = idx & 7;
            cp16(B + r * 128 + ((c ^ (r & 7)) << 4),
                 gd.X + (size_t)(bn0 + r) * DMODEL + k0 + c * 4);
        }
    };

    load_stage(0, 0);  CP_COMMIT();
    load_stage(1, BK); CP_COMMIT();

#pragma unroll 1
    for (int i = 0; i < 32; i++) {
        const int s = (i & 0x7fff) % 3;
        CP_WAIT1();                 // stage i resident
        __syncthreads();            // all warps done with the buffer being refilled

        if (i < 30) load_stage((i + 2) % 3, (i + 2) * BK);
        CP_COMMIT();

        const uint32_t A = sbase + s * STG;
        const uint32_t B = A + 16384;
#pragma unroll
        for (int kk = 0; kk < BK; kk += 8) {
            const int kc = kk >> 2;
            uint32_t af[4][4], bf[4][2];
#pragma unroll
            for (int mi = 0; mi < 4; mi++)
                ldsm4(af[mi][0], af[mi][1], af[mi][2], af[mi][3],
                      A + aoff[mi] + (((kc + akc) ^ lr) << 4));
#pragma unroll
            for (int g = 0; g < 2; g++)
                ldsm4(bf[g * 2][0], bf[g * 2][1], bf[g * 2 + 1][0], bf[g * 2 + 1][1],
                      B + boff[g] + (((kc + bkc) ^ lr) << 4));
#pragma unroll
            for (int mi = 0; mi < 4; mi++)
#pragma unroll
                for (int ni = 0; ni < 4; ni++)
                    mma_tf32(acc[mi][ni], af[mi], bf[ni][0], bf[ni][1]);
        }
    }

    // epilogue: bias + optional residual; optional transposed tf32 mirror
#pragma unroll
    for (int mi = 0; mi < 4; mi++) {
        int row0 = bm0 + wm + mi * 16 + gq;
        int row1 = row0 + 8;
        float b0 = gd.bias[row0], b1 = gd.bias[row1];
#pragma unroll
        for (int ni = 0; ni < 4; ni++) {
            int col = bn0 + wn + ni * 8 + tg * 2;
            size_t i0 = (size_t)row0 * NSEQ + col;
            size_t i1 = (size_t)row1 * NSEQ + col;
            float v00 = acc[mi][ni][0] + b0, v01 = acc[mi][ni][1] + b0;
            float v10 = acc[mi][ni][2] + b1, v11 = acc[mi][ni][3] + b1;
            if (gd.R) {
                v00 += gd.R[i0]; v01 += gd.R[i0 + 1];
                v10 += gd.R[i1]; v11 += gd.R[i1 + 1];
            }
            gd.Y[i0] = v00; gd.Y[i0 + 1] = v01;
            gd.Y[i1] = v10; gd.Y[i1 + 1] = v11;
            if (gd.Ytf) {
                gd.Ytf[(size_t)(col + 0) * DMODEL + row0] = __uint_as_float(f2tf32(v00));
                gd.Ytf[(size_t)(col + 1) * DMODEL + row0] = __uint_as_float(f2tf32(v01));
                gd.Ytf[(size_t)(col + 0) * DMODEL + row1] = __uint_as_float(f2tf32(v10));
                gd.Ytf[(size_t)(col + 1) * DMODEL + row1] = __uint_as_float(f2tf32(v11));
            }
        }
    }
}

// ---------------- tensor-core flash attention over d-slices ----------------
// Output written TRANSPOSED per item: XT[n][d*16+h], tf32-clean.

#define QSCALE (0.125f * 1.4426950408889634f)   // 1/sqrt(64) * log2(e)

__global__ __launch_bounds__(256) void flash_kernel(const float* __restrict__ Qb,
                                                    const float* __restrict__ Kb,
                                                    const float* __restrict__ Vb,
                                                    float* __restrict__ XTb) {
    extern __shared__ uint32_t fsm[];
    uint32_t* Ks = fsm;
    uint32_t* Vs = fsm + 16 * NSEQ;

    const int item = blockIdx.z;
    const int d    = blockIdx.x;
    const int nb   = blockIdx.y * 256;
    const int tid  = threadIdx.x;
    const int warp = tid >> 5;
    const int lane = tid & 31;
    const int gq   = lane >> 2;
    const int tg   = lane & 3;

    const float* Qg = Qb + (size_t)item * MN + (size_t)(d * 16) * NSEQ;
    const float* Kg = Kb + (size_t)item * MN + (size_t)(d * 16) * NSEQ;
    const float* Vg = Vb + (size_t)item * MN + (size_t)(d * 16) * NSEQ;
    float*       XT = XTb + (size_t)item * MN;

    const float4* K4 = (const float4*)Kg;
    const float4* V4 = (const float4*)Vg;
#pragma unroll
    for (int j = 0; j < 16; j++) {
        int idx = tid + j * 256;
        int h = idx >> 8;
        int m = (idx & 255) * 4;
        int c = m ^ ((h & 3) << 3);
        float4 kv = K4[idx];
        uint4 u;
        u.x = f2tf32(kv.x); u.y = f2tf32(kv.y); u.z = f2tf32(kv.z); u.w = f2tf32(kv.w);
        *(uint4*)&Ks[h * NSEQ + c] = u;
        float4 vv = V4[idx];
        uint4 w;
        w.x = f2tf32(vv.x); w.y = f2tf32(vv.y); w.z = f2tf32(vv.z); w.w = f2tf32(vv.w);
        *(uint4*)&Vs[h * NSEQ + c] = w;
    }
    __syncthreads();

    uint32_t qf[2][2][4];
#pragma unroll
    for (int mt = 0; mt < 2; mt++) {
        int n0 = nb + warp * 32 + mt * 16 + gq;
#pragma unroll
        for (int ks = 0; ks < 2; ks++) {
            int h = ks * 8 + tg;
            qf[mt][ks][0] = f2tf32(Qg[(size_t)h * NSEQ + n0] * QSCALE);
            qf[mt][ks][1] = f2tf32(Qg[(size_t)h * NSEQ + n0 + 8] * QSCALE);
            qf[mt][ks][2] = f2tf32(Qg[(size_t)(h + 4) * NSEQ + n0] * QSCALE);
            qf[mt][ks][3] = f2tf32(Qg[(size_t)(h + 4) * NSEQ + n0 + 8] * QSCALE);
        }
    }

    float xacc[2][2][4];
#pragma unroll
    for (int mt = 0; mt < 2; mt++)
#pragma unroll
        for (int ht = 0; ht < 2; ht++)
#pragma unroll
            for (int r = 0; r < 4; r++) xacc[mt][ht][r] = 0.f;
    float l[4] = {0.f, 0.f, 0.f, 0.f};

#pragma unroll 2
    for (int m0 = 0; m0 < NSEQ; m0 += 8) {
        int cm = (m0 + gq) ^ (tg << 3);
        uint32_t kf0 = Ks[tg * NSEQ + cm];
        uint32_t kf1 = Ks[(tg + 4) * NSEQ + cm];
        uint32_t kf2 = Ks[(tg + 8) * NSEQ + cm];
        uint32_t kf3 = Ks[(tg + 12) * NSEQ + cm];

        int cv = (m0 + 2 * tg) ^ ((gq & 3) << 3);
        uint2 vf0 = *(const uint2*)&Vs[gq * NSEQ + cv];
        uint2 vf1 = *(const uint2*)&Vs[(8 + gq) * NSEQ + cv];

#pragma unroll
        for (int mt = 0; mt < 2; mt++) {
            float s[4] = {0.f, 0.f, 0.f, 0.f};
            mma_tf32(s, qf[mt][0], kf0, kf1);
            mma_tf32(s, qf[mt][1], kf2, kf3);

            float p0 = ex2f(s[0]), p1 = ex2f(s[1]), p2 = ex2f(s[2]), p3 = ex2f(s[3]);
            l[mt * 2 + 0] += p0 + p1;
            l[mt * 2 + 1] += p2 + p3;

            uint32_t pa[4];
            pa[0] = f2tf32(p0); pa[1] = f2tf32(p2); pa[2] = f2tf32(p1); pa[3] = f2tf32(p3);

            mma_tf32(xacc[mt][0], pa, vf0.x, vf0.y);
            mma_tf32(xacc[mt][1], pa, vf1.x, vf1.y);
        }
    }

#pragma unroll
    for (int i = 0; i < 4; i++) {
        l[i] += __shfl_xor_sync(0xffffffffu, l[i], 1);
        l[i] += __shfl_xor_sync(0xffffffffu, l[i], 2);
    }
#pragma unroll
    for (int mt = 0; mt < 2; mt++) {
        float inv0 = 1.0f / l[mt * 2 + 0];
        float inv1 = 1.0f / l[mt * 2 + 1];
        int n0 = nb + warp * 32 + mt * 16 + gq;
#pragma unroll
        for (int ht = 0; ht < 2; ht++) {
            int h = d * 16 + ht * 8 + 2 * tg;
            float2 a, b;
            a.x = __uint_as_float(f2tf32(xacc[mt][ht][0] * inv0));
            a.y = __uint_as_float(f2tf32(xacc[mt][ht][1] * inv0));
            b.x = __uint_as_float(f2tf32(xacc[mt][ht][2] * inv1));
            b.y = __uint_as_float(f2tf32(xacc[mt][ht][3] * inv1));
            *(float2*)&XT[(size_t)n0 * DMODEL + h]       = a;
            *(float2*)&XT[(size_t)(n0 + 8) * DMODEL + h] = b;
        }
    }
}

// ---------------- launch ----------------
extern "C" void kernel_launch(void* const* d_in, const int* in_sizes, int n_in,
                              void* d_out, int out_size) {
    (void)in_sizes; (void)n_in; (void)out_size;

    const float* desc0 = (const float*)d_in[0];
    const float* desc1 = (const float*)d_in[1];
    const float* Wq = (const float*)d_in[2]; const float* bq = (const float*)d_in[3];
    const float* Wk = (const float*)d_in[4]; const float* bk = (const float*)d_in[5];
    const float* Wv = (const float*)d_in[6]; const float* bv = (const float*)d_in[7];
    const float* Wm = (const float*)d_in[8]; const float* bm = (const float*)d_in[9];

    float* out0 = (float*)d_out;
    float* out1 = out0 + MN;

    float *Qb, *Kb, *Vb, *Xb, *Wt, *Dt, *Tt;
    cudaGetSymbolAddress((void**)&Qb, g_Q);
    cudaGetSymbolAddress((void**)&Kb, g_K);
    cudaGetSymbolAddress((void**)&Vb, g_V);
    cudaGetSymbolAddress((void**)&Xb, g_X);
    cudaGetSymbolAddress((void**)&Wt, g_W);
    cudaGetSymbolAddress((void**)&Dt, g_D);
    cudaGetSymbolAddress((void**)&Tt, g_T);

    float* W0 = Wt;           float* W1 = Wt + MN;
    float* W2 = Wt + 2 * MN;  float* W3 = Wt + 3 * MN;
    float* D0 = Dt;           float* D1 = Dt + MN;   // transposed descs [n][c]
    float* T0 = Tt;           float* T1 = Tt + MN;   // transposed out mirrors [n][c]

    cudaFuncSetAttribute(conv_gemm, cudaFuncAttributeMaxDynamicSharedMemorySize, SMEM_CONV);
    cudaFuncSetAttribute(conv_gemm, cudaFuncAttributePreferredSharedMemoryCarveout,
                         cudaSharedmemCarveoutMaxShared);
    cudaFuncSetAttribute(flash_kernel, cudaFuncAttributeMaxDynamicSharedMemorySize, 131072);

    // ---- prep
    CvtBatch cb{};
    cb.s[0] = Wq; cb.d[0] = W0;
    cb.s[1] = Wk; cb.d[1] = W1;
    cb.s[2] = Wv; cb.d[2] = W2;
    cb.s[3] = Wm; cb.d[3] = W3;
    prep_round<<<dim3(1024, 4), 256>>>(cb);
    CvtTBatch ct{};
    ct.s[0] = desc0; ct.d[0] = D0;
    ct.s[1] = desc1; ct.d[1] = D1;
    prep_round_T<<<dim3(32, 32, 2), 256>>>(ct);

    // ---- attn1 (desc0 self) + attn2 (desc1 self): QKV GEMMs
    GemmBatch A{};
    A.g[0] = {W0, bq, D0, nullptr, Qb, nullptr};
    A.g[1] = {W1, bk, D0, nullptr, Kb, nullptr};
    A.g[2] = {W2, bv, D0, nullptr, Vb, nullptr};
    A.g[3] = {W0, bq, D1, nullptr, Qb + MN, nullptr};
    A.g[4] = {W1, bk, D1, nullptr, Kb + MN, nullptr};
    A.g[5] = {W2, bv, D1, nullptr, Vb + MN, nullptr};
    conv_gemm<<<dim3(8, 8, 6), 256, SMEM_CONV>>>(A);

    flash_kernel<<<dim3(64, 4, 2), 256, 131072>>>(Qb, Kb, Vb, Xb);

    // d0 = desc0 + Wm@X0 + bm ; d1 = desc1 + Wm@X1 + bm
    GemmBatch C{};
    C.g[0] = {W3, bm, Xb,      desc0, out0, T0};
    C.g[1] = {W3, bm, Xb + MN, desc1, out1, T1};
    conv_gemm<<<dim3(8, 8, 2), 256, SMEM_CONV>>>(C);

    // ---- attn3: q=d0, kv=d1
    GemmBatch Dq{};
    Dq.g[0] = {W0, bq, T0, nullptr, Qb, nullptr};
    Dq.g[1] = {W1, bk, T1, nullptr, Kb, nullptr};
    Dq.g[2] = {W2, bv, T1, nullptr, Vb, nullptr};
    conv_gemm<<<dim3(8, 8, 3), 256, SMEM_CONV>>>(Dq);

    flash_kernel<<<dim3(64, 4, 1), 256, 131072>>>(Qb, Kb, Vb, Xb);

    // ---- F (d0 += conv(x), refresh T0) merged with attn4's Q GEMM (needs only T1)
    GemmBatch FG{};
    FG.g[0] = {W3, bm, Xb, out0, out0, T0};
    FG.g[1] = {W0, bq, T1, nullptr, Qb, nullptr};
    conv_gemm<<<dim3(8, 8, 2), 256, SMEM_CONV>>>(FG);

    // ---- attn4 K,V GEMMs (need T0 from F)
    GemmBatch G{};
    G.g[0] = {W1, bk, T0, nullptr, Kb, nullptr};
    G.g[1] = {W2, bv, T0, nullptr, Vb, nullptr};
    conv_gemm<<<dim3(8, 8, 2), 256, SMEM_CONV>>>(G);

    flash_kernel<<<dim3(64, 4, 1), 256, 131072>>>(Qb, Kb, Vb, Xb);

    GemmBatch I{};
    I.g[0] = {W3, bm, Xb, out1, out1, nullptr};
    conv_gemm<<<dim3(8, 8, 1), 256, SMEM_CONV>>>(I);
}

// round 8
// speedup vs baseline: 2.5498x; 1.1906x over previous
#include <cuda_runtime.h>
#include <cstdint>

#define DMODEL 1024
#define NSEQ   1024
static const int MN = DMODEL * NSEQ;

// ---------------- scratch (device globals; no allocs allowed) ----------------
__device__ float g_Q[2 * 1024 * 1024];
__device__ float g_K[2 * 1024 * 1024];
__device__ float g_V[2 * 1024 * 1024];
__device__ float g_X[2 * 1024 * 1024];   // X^T per item: [n][c], tf32-clean
__device__ float g_W[4 * 1024 * 1024];   // tf32-rounded weights [m][k]
__device__ float g_D[2 * 1024 * 1024];   // desc0^T/desc1^T tf32-rounded [n][c]
__device__ float g_T[2 * 1024 * 1024];   // out0^T/out1^T tf32 mirrors [n][c]

__device__ __forceinline__ uint32_t f2tf32(float f) {
    uint32_t r;
    asm("cvt.rna.tf32.f32 %0, %1;" : "=r"(r) : "f"(f));
    return r;
}
__device__ __forceinline__ float ex2f(float x) {
    float y;
    asm("ex2.approx.f32 %0, %1;" : "=f"(y) : "f"(x));
    return y;
}
__device__ __forceinline__ void mma_tf32(float* d, const uint32_t* a, uint32_t b0, uint32_t b1) {
    asm volatile(
        "mma.sync.aligned.m16n8k8.row.col.f32.tf32.tf32.f32 "
        "{%0,%1,%2,%3}, {%4,%5,%6,%7}, {%8,%9}, {%0,%1,%2,%3};"
        : "+f"(d[0]), "+f"(d[1]), "+f"(d[2]), "+f"(d[3])
        : "r"(a[0]), "r"(a[1]), "r"(a[2]), "r"(a[3]), "r"(b0), "r"(b1));
}
__device__ __forceinline__ void ldsm4(uint32_t& r0, uint32_t& r1, uint32_t& r2, uint32_t& r3,
                                      uint32_t addr) {
    asm volatile("ldmatrix.sync.aligned.m8n8.x4.shared.b16 {%0,%1,%2,%3}, [%4];"
                 : "=r"(r0), "=r"(r1), "=r"(r2), "=r"(r3) : "r"(addr));
}
__device__ __forceinline__ void cp16(uint32_t dst, const void* src) {
    asm volatile("cp.async.cg.shared.global [%0], [%1], 16;" :: "r"(dst), "l"(src));
}
#define CP_COMMIT() asm volatile("cp.async.commit_group;")
#define CP_WAIT1()  asm volatile("cp.async.wait_group 1;")

// ---------------- prep: tf32-round weights; transpose+round descs ------------
struct CvtBatch { const float* s[4]; float* d[4]; };

__global__ __launch_bounds__(256) void prep_round(CvtBatch cb) {
    const float4* s = (const float4*)cb.s[blockIdx.y];
    uint4*        d = (uint4*)cb.d[blockIdx.y];
    int i = blockIdx.x * 256 + threadIdx.x;
    float4 v = s[i];
    uint4 u;
    u.x = f2tf32(v.x); u.y = f2tf32(v.y); u.z = f2tf32(v.z); u.w = f2tf32(v.w);
    d[i] = u;
}

struct CvtTBatch { const float* s[2]; float* d[2]; };

// dst[n][c] = tf32(src[c][n])
__global__ __launch_bounds__(256) void prep_round_T(CvtTBatch cb) {
    __shared__ float t[32][33];
    const float* src = cb.s[blockIdx.z];
    float*       dst = cb.d[blockIdx.z];
    int tx = threadIdx.x & 31, ty = threadIdx.x >> 5;
    int cb0 = blockIdx.y * 32, nb0 = blockIdx.x * 32;
#pragma unroll
    for (int j = 0; j < 4; j++)
        t[ty + j * 8][tx] = src[(size_t)(cb0 + ty + j * 8) * NSEQ + nb0 + tx];
    __syncthreads();
#pragma unroll
    for (int j = 0; j < 4; j++)
        dst[(size_t)(nb0 + ty + j * 8) * DMODEL + cb0 + tx] =
            __uint_as_float(f2tf32(t[tx][ty + j * 8]));
}

// ---------------- tf32 GEMM: ldmatrix fragments, 3-stage/1-sync pipeline -----
struct GemmDesc { const float *W, *bias, *X, *R; float *Y, *Ytf; };
struct GemmBatch { GemmDesc g[6]; };

constexpr int BK = 32;
constexpr int STG = 32768;                 // A 16KB + B 16KB
constexpr int SMEM_CONV = 3 * STG;         // 98304 B

__global__ __launch_bounds__(256, 2) void conv_gemm(GemmBatch batch) {
    const GemmDesc gd = batch.g[blockIdx.z];
    extern __shared__ char smem[];
    const uint32_t sbase = (uint32_t)__cvta_generic_to_shared(smem);

    const int tid  = threadIdx.x;
    const int lane = tid & 31;
    const int warp = tid >> 5;
    const int gq   = lane >> 2;
    const int tg   = lane & 3;
    const int wm   = (warp >> 2) * 64;
    const int wn   = (warp & 3) * 32;
    const int bm0  = blockIdx.x * 128;
    const int bn0  = blockIdx.y * 128;

    float acc[4][4][4];
#pragma unroll
    for (int mi = 0; mi < 4; mi++)
#pragma unroll
        for (int ni = 0; ni < 4; ni++)
#pragma unroll
            for (int r = 0; r < 4; r++) acc[mi][ni][r] = 0.f;

    const int lj = lane >> 3;
    const int lr = lane & 7;
    uint32_t aoff[4];
#pragma unroll
    for (int mi = 0; mi < 4; mi++)
        aoff[mi] = (uint32_t)(wm + mi * 16 + (lj & 1) * 8 + lr) * 128;
    const int akc = lj >> 1;
    uint32_t boff[2];
#pragma unroll
    for (int g = 0; g < 2; g++)
        boff[g] = (uint32_t)(wn + g * 16 + (lj >> 1) * 8 + lr) * 128;
    const int bkc = lj & 1;

    auto load_stage = [&](int stg, int k0) {
        uint32_t A = sbase + stg * STG;
        uint32_t B = A + 16384;
#pragma unroll
        for (int j = 0; j < 4; j++) {
            int idx = tid + j * 256;
            int r = idx >> 3, c = idx & 7;
            cp16(A + r * 128 + ((c ^ (r & 7)) << 4),
                 gd.W + (size_t)(bm0 + r) * DMODEL + k0 + c * 4);
        }
#pragma unroll
        for (int j = 0; j < 4; j++) {
            int idx = tid + j * 256;
            int r = idx >> 3, c = idx & 7;
            cp16(B + r * 128 + ((c ^ (r & 7)) << 4),
                 gd.X + (size_t)(bn0 + r) * DMODEL + k0 + c * 4);
        }
    };

    load_stage(0, 0);  CP_COMMIT();
    load_stage(1, BK); CP_COMMIT();

#pragma unroll 1
    for (int i = 0; i < 32; i++) {
        const int s = (i & 0x7fff) % 3;
        CP_WAIT1();
        __syncthreads();

        if (i < 30) load_stage((i + 2) % 3, (i + 2) * BK);
        CP_COMMIT();

        const uint32_t A = sbase + s * STG;
        const uint32_t B = A + 16384;
#pragma unroll
        for (int kk = 0; kk < BK; kk += 8) {
            const int kc = kk >> 2;
            uint32_t af[4][4], bf[4][2];
#pragma unroll
            for (int mi = 0; mi < 4; mi++)
                ldsm4(af[mi][0], af[mi][1], af[mi][2], af[mi][3],
                      A + aoff[mi] + (((kc + akc) ^ lr) << 4));
#pragma unroll
            for (int g = 0; g < 2; g++)
                ldsm4(bf[g * 2][0], bf[g * 2][1], bf[g * 2 + 1][0], bf[g * 2 + 1][1],
                      B + boff[g] + (((kc + bkc) ^ lr) << 4));
#pragma unroll
            for (int mi = 0; mi < 4; mi++)
#pragma unroll
                for (int ni = 0; ni < 4; ni++)
                    mma_tf32(acc[mi][ni], af[mi], bf[ni][0], bf[ni][1]);
        }
    }

#pragma unroll
    for (int mi = 0; mi < 4; mi++) {
        int row0 = bm0 + wm + mi * 16 + gq;
        int row1 = row0 + 8;
        float b0 = gd.bias[row0], b1 = gd.bias[row1];
#pragma unroll
        for (int ni = 0; ni < 4; ni++) {
            int col = bn0 + wn + ni * 8 + tg * 2;
            size_t i0 = (size_t)row0 * NSEQ + col;
            size_t i1 = (size_t)row1 * NSEQ + col;
            float v00 = acc[mi][ni][0] + b0, v01 = acc[mi][ni][1] + b0;
            float v10 = acc[mi][ni][2] + b1, v11 = acc[mi][ni][3] + b1;
            if (gd.R) {
                v00 += gd.R[i0]; v01 += gd.R[i0 + 1];
                v10 += gd.R[i1]; v11 += gd.R[i1 + 1];
            }
            gd.Y[i0] = v00; gd.Y[i0 + 1] = v01;
            gd.Y[i1] = v10; gd.Y[i1 + 1] = v11;
            if (gd.Ytf) {
                gd.Ytf[(size_t)(col + 0) * DMODEL + row0] = __uint_as_float(f2tf32(v00));
                gd.Ytf[(size_t)(col + 1) * DMODEL + row0] = __uint_as_float(f2tf32(v01));
                gd.Ytf[(size_t)(col + 0) * DMODEL + row1] = __uint_as_float(f2tf32(v10));
                gd.Ytf[(size_t)(col + 1) * DMODEL + row1] = __uint_as_float(f2tf32(v11));
            }
        }
    }
}

// ---------------- flash attention: split-KV (2 x 512 cols), 3 CTAs/SM -------
// Output TRANSPOSED per item: XT[n][d*16+h], tf32-clean.

#define QSCALE (0.125f * 1.4426950408889634f)   // 1/sqrt(64) * log2(e)
constexpr int HC = 512;                          // columns per KV pass
constexpr int SMEM_FLASH = 2 * 16 * HC * 4;      // 65536 B

__global__ __launch_bounds__(256) void flash_kernel(const float* __restrict__ Qb,
                                                    const float* __restrict__ Kb,
                                                    const float* __restrict__ Vb,
                                                    float* __restrict__ XTb) {
    extern __shared__ uint32_t fsm[];
    uint32_t* Ks = fsm;                  // [16][512] tf32 bits, swizzled
    uint32_t* Vs = fsm + 16 * HC;

    const int item = blockIdx.z;
    const int d    = blockIdx.x;
    const int nb   = blockIdx.y * 256;
    const int tid  = threadIdx.x;
    const int warp = tid >> 5;
    const int lane = tid & 31;
    const int gq   = lane >> 2;
    const int tg   = lane & 3;

    const float* Qg = Qb + (size_t)item * MN + (size_t)(d * 16) * NSEQ;
    const float* Kg = Kb + (size_t)item * MN + (size_t)(d * 16) * NSEQ;
    const float* Vg = Vb + (size_t)item * MN + (size_t)(d * 16) * NSEQ;
    float*       XT = XTb + (size_t)item * MN;

    // Q fragments (scale folded)
    uint32_t qf[2][2][4];
#pragma unroll
    for (int mt = 0; mt < 2; mt++) {
        int n0 = nb + warp * 32 + mt * 16 + gq;
#pragma unroll
        for (int ks = 0; ks < 2; ks++) {
            int h = ks * 8 + tg;
            qf[mt][ks][0] = f2tf32(Qg[(size_t)h * NSEQ + n0] * QSCALE);
            qf[mt][ks][1] = f2tf32(Qg[(size_t)h * NSEQ + n0 + 8] * QSCALE);
            qf[mt][ks][2] = f2tf32(Qg[(size_t)(h + 4) * NSEQ + n0] * QSCALE);
            qf[mt][ks][3] = f2tf32(Qg[(size_t)(h + 4) * NSEQ + n0 + 8] * QSCALE);
        }
    }

    float xacc[2][2][4];
#pragma unroll
    for (int mt = 0; mt < 2; mt++)
#pragma unroll
        for (int ht = 0; ht < 2; ht++)
#pragma unroll
            for (int r = 0; r < 4; r++) xacc[mt][ht][r] = 0.f;
    float l[4] = {0.f, 0.f, 0.f, 0.f};

#pragma unroll 1
    for (int half = 0; half < 2; half++) {
        // fill K/V half-tiles: 2048 float4 each (16 rows x 128 float4)
#pragma unroll
        for (int j = 0; j < 8; j++) {
            int idx = tid + j * 256;
            int h = idx >> 7;
            int m4 = idx & 127;
            int c = (m4 * 4) ^ ((h & 3) << 3);
            const float4 kv = *(const float4*)&Kg[(size_t)h * NSEQ + half * HC + m4 * 4];
            uint4 u;
            u.x = f2tf32(kv.x); u.y = f2tf32(kv.y); u.z = f2tf32(kv.z); u.w = f2tf32(kv.w);
            *(uint4*)&Ks[h * HC + c] = u;
            const float4 vv = *(const float4*)&Vg[(size_t)h * NSEQ + half * HC + m4 * 4];
            uint4 w;
            w.x = f2tf32(vv.x); w.y = f2tf32(vv.y); w.z = f2tf32(vv.z); w.w = f2tf32(vv.w);
            *(uint4*)&Vs[h * HC + c] = w;
        }
        __syncthreads();

#pragma unroll 2
        for (int m0 = 0; m0 < HC; m0 += 8) {
            int cm = (m0 + gq) ^ (tg << 3);
            uint32_t kf0 = Ks[tg * HC + cm];
            uint32_t kf1 = Ks[(tg + 4) * HC + cm];
            uint32_t kf2 = Ks[(tg + 8) * HC + cm];
            uint32_t kf3 = Ks[(tg + 12) * HC + cm];

            int cv = (m0 + 2 * tg) ^ ((gq & 3) << 3);
            uint2 vf0 = *(const uint2*)&Vs[gq * HC + cv];
            uint2 vf1 = *(const uint2*)&Vs[(8 + gq) * HC + cv];

#pragma unroll
            for (int mt = 0; mt < 2; mt++) {
                float s[4] = {0.f, 0.f, 0.f, 0.f};
                mma_tf32(s, qf[mt][0], kf0, kf1);
                mma_tf32(s, qf[mt][1], kf2, kf3);

                float p0 = ex2f(s[0]), p1 = ex2f(s[1]), p2 = ex2f(s[2]), p3 = ex2f(s[3]);
                l[mt * 2 + 0] += p0 + p1;
                l[mt * 2 + 1] += p2 + p3;

                uint32_t pa[4];
                pa[0] = f2tf32(p0); pa[1] = f2tf32(p2); pa[2] = f2tf32(p1); pa[3] = f2tf32(p3);

                mma_tf32(xacc[mt][0], pa, vf0.x, vf0.y);
                mma_tf32(xacc[mt][1], pa, vf1.x, vf1.y);
            }
        }
        __syncthreads();    // all warps done reading before refill
    }

#pragma unroll
    for (int i = 0; i < 4; i++) {
        l[i] += __shfl_xor_sync(0xffffffffu, l[i], 1);
        l[i] += __shfl_xor_sync(0xffffffffu, l[i], 2);
    }
#pragma unroll
    for (int mt = 0; mt < 2; mt++) {
        float inv0 = 1.0f / l[mt * 2 + 0];
        float inv1 = 1.0f / l[mt * 2 + 1];
        int n0 = nb + warp * 32 + mt * 16 + gq;
#pragma unroll
        for (int ht = 0; ht < 2; ht++) {
            int h = d * 16 + ht * 8 + 2 * tg;
            float2 a, b;
            a.x = __uint_as_float(f2tf32(xacc[mt][ht][0] * inv0));
            a.y = __uint_as_float(f2tf32(xacc[mt][ht][1] * inv0));
            b.x = __uint_as_float(f2tf32(xacc[mt][ht][2] * inv1));
            b.y = __uint_as_float(f2tf32(xacc[mt][ht][3] * inv1));
            *(float2*)&XT[(size_t)n0 * DMODEL + h]       = a;
            *(float2*)&XT[(size_t)(n0 + 8) * DMODEL + h] = b;
        }
    }
}

// ---------------- launch ----------------
extern "C" void kernel_launch(void* const* d_in, const int* in_sizes, int n_in,
                              void* d_out, int out_size) {
    (void)in_sizes; (void)n_in; (void)out_size;

    const float* desc0 = (const float*)d_in[0];
    const float* desc1 = (const float*)d_in[1];
    const float* Wq = (const float*)d_in[2]; const float* bq = (const float*)d_in[3];
    const float* Wk = (const float*)d_in[4]; const float* bk = (const float*)d_in[5];
    const float* Wv = (const float*)d_in[6]; const float* bv = (const float*)d_in[7];
    const float* Wm = (const float*)d_in[8]; const float* bm = (const float*)d_in[9];

    float* out0 = (float*)d_out;
    float* out1 = out0 + MN;

    float *Qb, *Kb, *Vb, *Xb, *Wt, *Dt, *Tt;
    cudaGetSymbolAddress((void**)&Qb, g_Q);
    cudaGetSymbolAddress((void**)&Kb, g_K);
    cudaGetSymbolAddress((void**)&Vb, g_V);
    cudaGetSymbolAddress((void**)&Xb, g_X);
    cudaGetSymbolAddress((void**)&Wt, g_W);
    cudaGetSymbolAddress((void**)&Dt, g_D);
    cudaGetSymbolAddress((void**)&Tt, g_T);

    float* W0 = Wt;           float* W1 = Wt + MN;
    float* W2 = Wt + 2 * MN;  float* W3 = Wt + 3 * MN;
    float* D0 = Dt;           float* D1 = Dt + MN;
    float* T0 = Tt;           float* T1 = Tt + MN;

    cudaFuncSetAttribute(conv_gemm, cudaFuncAttributeMaxDynamicSharedMemorySize, SMEM_CONV);
    cudaFuncSetAttribute(conv_gemm, cudaFuncAttributePreferredSharedMemoryCarveout,
                         cudaSharedmemCarveoutMaxShared);
    cudaFuncSetAttribute(flash_kernel, cudaFuncAttributeMaxDynamicSharedMemorySize, SMEM_FLASH);
    cudaFuncSetAttribute(flash_kernel, cudaFuncAttributePreferredSharedMemoryCarveout,
                         cudaSharedmemCarveoutMaxShared);

    // ---- prep
    CvtBatch cb{};
    cb.s[0] = Wq; cb.d[0] = W0;
    cb.s[1] = Wk; cb.d[1] = W1;
    cb.s[2] = Wv; cb.d[2] = W2;
    cb.s[3] = Wm; cb.d[3] = W3;
    prep_round<<<dim3(1024, 4), 256>>>(cb);
    CvtTBatch ct{};
    ct.s[0] = desc0; ct.d[0] = D0;
    ct.s[1] = desc1; ct.d[1] = D1;
    prep_round_T<<<dim3(32, 32, 2), 256>>>(ct);

    // ---- attn1 (desc0 self) + attn2 (desc1 self): QKV GEMMs
    GemmBatch A{};
    A.g[0] = {W0, bq, D0, nullptr, Qb, nullptr};
    A.g[1] = {W1, bk, D0, nullptr, Kb, nullptr};
    A.g[2] = {W2, bv, D0, nullptr, Vb, nullptr};
    A.g[3] = {W0, bq, D1, nullptr, Qb + MN, nullptr};
    A.g[4] = {W1, bk, D1, nullptr, Kb + MN, nullptr};
    A.g[5] = {W2, bv, D1, nullptr, Vb + MN, nullptr};
    conv_gemm<<<dim3(8, 8, 6), 256, SMEM_CONV>>>(A);

    flash_kernel<<<dim3(64, 4, 2), 256, SMEM_FLASH>>>(Qb, Kb, Vb, Xb);

    // d0 = desc0 + Wm@X0 + bm ; d1 = desc1 + Wm@X1 + bm
    GemmBatch C{};
    C.g[0] = {W3, bm, Xb,      desc0, out0, T0};
    C.g[1] = {W3, bm, Xb + MN, desc1, out1, T1};
    conv_gemm<<<dim3(8, 8, 2), 256, SMEM_CONV>>>(C);

    // ---- attn3: q=d0, kv=d1
    GemmBatch Dq{};
    Dq.g[0] = {W0, bq, T0, nullptr, Qb, nullptr};
    Dq.g[1] = {W1, bk, T1, nullptr, Kb, nullptr};
    Dq.g[2] = {W2, bv, T1, nullptr, Vb, nullptr};
    conv_gemm<<<dim3(8, 8, 3), 256, SMEM_CONV>>>(Dq);

    flash_kernel<<<dim3(64, 4, 1), 256, SMEM_FLASH>>>(Qb, Kb, Vb, Xb);

    // ---- F (d0 += conv(x), refresh T0) merged with attn4's Q GEMM (needs only T1)
    GemmBatch FG{};
    FG.g[0] = {W3, bm, Xb, out0, out0, T0};
    FG.g[1] = {W0, bq, T1, nullptr, Qb, nullptr};
    conv_gemm<<<dim3(8, 8, 2), 256, SMEM_CONV>>>(FG);

    // ---- attn4 K,V GEMMs (need T0 from F)
    GemmBatch G{};
    G.g[0] = {W1, bk, T0, nullptr, Kb, nullptr};
    G.g[1] = {W2, bv, T0, nullptr, Vb, nullptr};
    conv_gemm<<<dim3(8, 8, 2), 256, SMEM_CONV>>>(G);

    flash_kernel<<<dim3(64, 4, 1), 256, SMEM_FLASH>>>(Qb, Kb, Vb, Xb);

    GemmBatch I{};
    I.g[0] = {W3, bm, Xb, out1, out1, nullptr};
    conv_gemm<<<dim3(8, 8, 1), 256, SMEM_CONV>>>(I);
}

// round 9
// speedup vs baseline: 2.7000x; 1.0589x over previous
#include <cuda_runtime.h>
#include <cstdint>

#define DMODEL 1024
#define NSEQ   1024
static const int MN = DMODEL * NSEQ;

// ---------------- scratch (device globals; no allocs allowed) ----------------
__device__ float g_Q[2 * 1024 * 1024];
__device__ float g_K[2 * 1024 * 1024];
__device__ float g_V[2 * 1024 * 1024];
__device__ float g_X[2 * 1024 * 1024];   // X^T per item: [n][c], tf32-clean
__device__ float g_W[4 * 1024 * 1024];   // tf32-rounded weights [m][k]
__device__ float g_D[2 * 1024 * 1024];   // desc0^T/desc1^T tf32-rounded [n][c]
__device__ float g_T[2 * 1024 * 1024];   // out0^T/out1^T tf32 mirrors [n][c]

__device__ __forceinline__ uint32_t f2tf32(float f) {
    uint32_t r;
    asm("cvt.rna.tf32.f32 %0, %1;" : "=r"(r) : "f"(f));
    return r;
}
__device__ __forceinline__ float ex2f(float x) {
    float y;
    asm("ex2.approx.f32 %0, %1;" : "=f"(y) : "f"(x));
    return y;
}
__device__ __forceinline__ void mma_tf32(float* d, const uint32_t* a, uint32_t b0, uint32_t b1) {
    asm volatile(
        "mma.sync.aligned.m16n8k8.row.col.f32.tf32.tf32.f32 "
        "{%0,%1,%2,%3}, {%4,%5,%6,%7}, {%8,%9}, {%0,%1,%2,%3};"
        : "+f"(d[0]), "+f"(d[1]), "+f"(d[2]), "+f"(d[3])
        : "r"(a[0]), "r"(a[1]), "r"(a[2]), "r"(a[3]), "r"(b0), "r"(b1));
}
__device__ __forceinline__ void ldsm4(uint32_t& r0, uint32_t& r1, uint32_t& r2, uint32_t& r3,
                                      uint32_t addr) {
    asm volatile("ldmatrix.sync.aligned.m8n8.x4.shared.b16 {%0,%1,%2,%3}, [%4];"
                 : "=r"(r0), "=r"(r1), "=r"(r2), "=r"(r3) : "r"(addr));
}
__device__ __forceinline__ void cp16(uint32_t dst, const void* src) {
    asm volatile("cp.async.cg.shared.global [%0], [%1], 16;" :: "r"(dst), "l"(src));
}
#define CP_COMMIT() asm volatile("cp.async.commit_group;")
#define CP_WAIT1()  asm volatile("cp.async.wait_group 1;")

// ---------------- prep: tf32-round weights; transpose+round descs ------------
struct CvtBatch { const float* s[4]; float* d[4]; };

__global__ __launch_bounds__(256) void prep_round(CvtBatch cb) {
    const float4* s = (const float4*)cb.s[blockIdx.y];
    uint4*        d = (uint4*)cb.d[blockIdx.y];
    int i = blockIdx.x * 256 + threadIdx.x;
    float4 v = s[i];
    uint4 u;
    u.x = f2tf32(v.x); u.y = f2tf32(v.y); u.z = f2tf32(v.z); u.w = f2tf32(v.w);
    d[i] = u;
}

struct CvtTBatch { const float* s[2]; float* d[2]; };

// dst[n][c] = tf32(src[c][n])
__global__ __launch_bounds__(256) void prep_round_T(CvtTBatch cb) {
    __shared__ float t[32][33];
    const float* src = cb.s[blockIdx.z];
    float*       dst = cb.d[blockIdx.z];
    int tx = threadIdx.x & 31, ty = threadIdx.x >> 5;
    int cb0 = blockIdx.y * 32, nb0 = blockIdx.x * 32;
#pragma unroll
    for (int j = 0; j < 4; j++)
        t[ty + j * 8][tx] = src[(size_t)(cb0 + ty + j * 8) * NSEQ + nb0 + tx];
    __syncthreads();
#pragma unroll
    for (int j = 0; j < 4; j++)
        dst[(size_t)(nb0 + ty + j * 8) * DMODEL + cb0 + tx] =
            __uint_as_float(f2tf32(t[tx][ty + j * 8]));
}

// ---------------- tf32 GEMM: 64x128 tiles, ldmatrix, 3-stage pipeline --------
// Y[m,n] = sum_k W[m,k] * Bt[n,k] + bias[m] (+R).  W [m][k], Bt [n][k].
// grid (16, 8, z): 128 CTAs per GEMM.

struct GemmDesc { const float *W, *bias, *X, *R; float *Y, *Ytf; };
struct GemmBatch { GemmDesc g[6]; };

constexpr int BK = 32;
constexpr int ASZ = 8192;                  // A: 64 rows x 128 B
constexpr int BSZ = 16384;                 // B: 128 rows x 128 B
constexpr int STG = ASZ + BSZ;             // 24576 B / stage
constexpr int SMEM_CONV = 3 * STG;         // 73728 B

__global__ __launch_bounds__(256, 2) void conv_gemm(GemmBatch batch) {
    const GemmDesc gd = batch.g[blockIdx.z];
    extern __shared__ char smem[];
    const uint32_t sbase = (uint32_t)__cvta_generic_to_shared(smem);

    const int tid  = threadIdx.x;
    const int lane = tid & 31;
    const int warp = tid >> 5;
    const int gq   = lane >> 2;
    const int tg   = lane & 3;
    const int wm   = (warp >> 2) * 32;     // 2 m-tiles of 16 per warp
    const int wn   = (warp & 3) * 32;
    const int bm0  = blockIdx.x * 64;
    const int bn0  = blockIdx.y * 128;

    float acc[2][4][4];
#pragma unroll
    for (int mi = 0; mi < 2; mi++)
#pragma unroll
        for (int ni = 0; ni < 4; ni++)
#pragma unroll
            for (int r = 0; r < 4; r++) acc[mi][ni][r] = 0.f;

    const int lj = lane >> 3;
    const int lr = lane & 7;
    uint32_t aoff[2];
#pragma unroll
    for (int mi = 0; mi < 2; mi++)
        aoff[mi] = (uint32_t)(wm + mi * 16 + (lj & 1) * 8 + lr) * 128;
    const int akc = lj >> 1;
    uint32_t boff[2];
#pragma unroll
    for (int g = 0; g < 2; g++)
        boff[g] = (uint32_t)(wn + g * 16 + (lj >> 1) * 8 + lr) * 128;
    const int bkc = lj & 1;

    auto load_stage = [&](int stg, int k0) {
        uint32_t A = sbase + stg * STG;
        uint32_t B = A + ASZ;
#pragma unroll
        for (int j = 0; j < 2; j++) {              // A: 512 x 16B
            int idx = tid + j * 256;
            int r = idx >> 3, c = idx & 7;
            cp16(A + r * 128 + ((c ^ (r & 7)) << 4),
                 gd.W + (size_t)(bm0 + r) * DMODEL + k0 + c * 4);
        }
#pragma unroll
        for (int j = 0; j < 4; j++) {              // B: 1024 x 16B
            int idx = tid + j * 256;
            int r = idx >> 3, c = idx & 7;
            cp16(B + r * 128 + ((c ^ (r & 7)) << 4),
                 gd.X + (size_t)(bn0 + r) * DMODEL + k0 + c * 4);
        }
    };

    load_stage(0, 0);  CP_COMMIT();
    load_stage(1, BK); CP_COMMIT();

#pragma unroll 1
    for (int i = 0; i < 32; i++) {
        const int s = (i & 0x7fff) % 3;
        CP_WAIT1();
        __syncthreads();

        if (i < 30) load_stage((i + 2) % 3, (i + 2) * BK);
        CP_COMMIT();

        const uint32_t A = sbase + s * STG;
        const uint32_t B = A + ASZ;
#pragma unroll
        for (int kk = 0; kk < BK; kk += 8) {
            const int kc = kk >> 2;
            uint32_t af[2][4], bf[4][2];
#pragma unroll
            for (int mi = 0; mi < 2; mi++)
                ldsm4(af[mi][0], af[mi][1], af[mi][2], af[mi][3],
                      A + aoff[mi] + (((kc + akc) ^ lr) << 4));
#pragma unroll
            for (int g = 0; g < 2; g++)
                ldsm4(bf[g * 2][0], bf[g * 2][1], bf[g * 2 + 1][0], bf[g * 2 + 1][1],
                      B + boff[g] + (((kc + bkc) ^ lr) << 4));
#pragma unroll
            for (int mi = 0; mi < 2; mi++)
#pragma unroll
                for (int ni = 0; ni < 4; ni++)
                    mma_tf32(acc[mi][ni], af[mi], bf[ni][0], bf[ni][1]);
        }
    }

#pragma unroll
    for (int mi = 0; mi < 2; mi++) {
        int row0 = bm0 + wm + mi * 16 + gq;
        int row1 = row0 + 8;
        float b0 = gd.bias[row0], b1 = gd.bias[row1];
#pragma unroll
        for (int ni = 0; ni < 4; ni++) {
            int col = bn0 + wn + ni * 8 + tg * 2;
            size_t i0 = (size_t)row0 * NSEQ + col;
            size_t i1 = (size_t)row1 * NSEQ + col;
            float v00 = acc[mi][ni][0] + b0, v01 = acc[mi][ni][1] + b0;
            float v10 = acc[mi][ni][2] + b1, v11 = acc[mi][ni][3] + b1;
            if (gd.R) {
                v00 += gd.R[i0]; v01 += gd.R[i0 + 1];
                v10 += gd.R[i1]; v11 += gd.R[i1 + 1];
            }
            gd.Y[i0] = v00; gd.Y[i0 + 1] = v01;
            gd.Y[i1] = v10; gd.Y[i1 + 1] = v11;
            if (gd.Ytf) {
                gd.Ytf[(size_t)(col + 0) * DMODEL + row0] = __uint_as_float(f2tf32(v00));
                gd.Ytf[(size_t)(col + 1) * DMODEL + row0] = __uint_as_float(f2tf32(v01));
                gd.Ytf[(size_t)(col + 0) * DMODEL + row1] = __uint_as_float(f2tf32(v10));
                gd.Ytf[(size_t)(col + 1) * DMODEL + row1] = __uint_as_float(f2tf32(v11));
            }
        }
    }
}

// ---------------- flash attention: split-KV (2 x 512 cols), 3 CTAs/SM -------
// Output TRANSPOSED per item: XT[n][d*16+h], tf32-clean.

#define QSCALE (0.125f * 1.4426950408889634f)   // 1/sqrt(64) * log2(e)
constexpr int HC = 512;                          // columns per KV pass
constexpr int SMEM_FLASH = 2 * 16 * HC * 4;      // 65536 B

__global__ __launch_bounds__(256) void flash_kernel(const float* __restrict__ Qb,
                                                    const float* __restrict__ Kb,
                                                    const float* __restrict__ Vb,
                                                    float* __restrict__ XTb) {
    extern __shared__ uint32_t fsm[];
    uint32_t* Ks = fsm;                  // [16][512] tf32 bits, swizzled
    uint32_t* Vs = fsm + 16 * HC;

    const int item = blockIdx.z;
    const int d    = blockIdx.x;
    const int nb   = blockIdx.y * 256;
    const int tid  = threadIdx.x;
    const int warp = tid >> 5;
    const int lane = tid & 31;
    const int gq   = lane >> 2;
    const int tg   = lane & 3;

    const float* Qg = Qb + (size_t)item * MN + (size_t)(d * 16) * NSEQ;
    const float* Kg = Kb + (size_t)item * MN + (size_t)(d * 16) * NSEQ;
    const float* Vg = Vb + (size_t)item * MN + (size_t)(d * 16) * NSEQ;
    float*       XT = XTb + (size_t)item * MN;

    uint32_t qf[2][2][4];
#pragma unroll
    for (int mt = 0; mt < 2; mt++) {
        int n0 = nb + warp * 32 + mt * 16 + gq;
#pragma unroll
        for (int ks = 0; ks < 2; ks++) {
            int h = ks * 8 + tg;
            qf[mt][ks][0] = f2tf32(Qg[(size_t)h * NSEQ + n0] * QSCALE);
            qf[mt][ks][1] = f2tf32(Qg[(size_t)h * NSEQ + n0 + 8] * QSCALE);
            qf[mt][ks][2] = f2tf32(Qg[(size_t)(h + 4) * NSEQ + n0] * QSCALE);
            qf[mt][ks][3] = f2tf32(Qg[(size_t)(h + 4) * NSEQ + n0 + 8] * QSCALE);
        }
    }

    float xacc[2][2][4];
#pragma unroll
    for (int mt = 0; mt < 2; mt++)
#pragma unroll
        for (int ht = 0; ht < 2; ht++)
#pragma unroll
            for (int r = 0; r < 4; r++) xacc[mt][ht][r] = 0.f;
    float l[4] = {0.f, 0.f, 0.f, 0.f};

#pragma unroll 1
    for (int half = 0; half < 2; half++) {
#pragma unroll
        for (int j = 0; j < 8; j++) {
            int idx = tid + j * 256;
            int h = idx >> 7;
            int m4 = idx & 127;
            int c = (m4 * 4) ^ ((h & 3) << 3);
            const float4 kv = *(const float4*)&Kg[(size_t)h * NSEQ + half * HC + m4 * 4];
            uint4 u;
            u.x = f2tf32(kv.x); u.y = f2tf32(kv.y); u.z = f2tf32(kv.z); u.w = f2tf32(kv.w);
            *(uint4*)&Ks[h * HC + c] = u;
            const float4 vv = *(const float4*)&Vg[(size_t)h * NSEQ + half * HC + m4 * 4];
            uint4 w;
            w.x = f2tf32(vv.x); w.y = f2tf32(vv.y); w.z = f2tf32(vv.z); w.w = f2tf32(vv.w);
            *(uint4*)&Vs[h * HC + c] = w;
        }
        __syncthreads();

#pragma unroll 2
        for (int m0 = 0; m0 < HC; m0 += 8) {
            int cm = (m0 + gq) ^ (tg << 3);
            uint32_t kf0 = Ks[tg * HC + cm];
            uint32_t kf1 = Ks[(tg + 4) * HC + cm];
            uint32_t kf2 = Ks[(tg + 8) * HC + cm];
            uint32_t kf3 = Ks[(tg + 12) * HC + cm];

            int cv = (m0 + 2 * tg) ^ ((gq & 3) << 3);
            uint2 vf0 = *(const uint2*)&Vs[gq * HC + cv];
            uint2 vf1 = *(const uint2*)&Vs[(8 + gq) * HC + cv];

#pragma unroll
            for (int mt = 0; mt < 2; mt++) {
                float s[4] = {0.f, 0.f, 0.f, 0.f};
                mma_tf32(s, qf[mt][0], kf0, kf1);
                mma_tf32(s, qf[mt][1], kf2, kf3);

                float p0 = ex2f(s[0]), p1 = ex2f(s[1]), p2 = ex2f(s[2]), p3 = ex2f(s[3]);
                l[mt * 2 + 0] += p0 + p1;
                l[mt * 2 + 1] += p2 + p3;

                // feed P as raw fp32 bits (tf32 reads high bits; truncation)
                uint32_t pa[4];
                pa[0] = __float_as_uint(p0); pa[1] = __float_as_uint(p2);
                pa[2] = __float_as_uint(p1); pa[3] = __float_as_uint(p3);

                mma_tf32(xacc[mt][0], pa, vf0.x, vf0.y);
                mma_tf32(xacc[mt][1], pa, vf1.x, vf1.y);
            }
        }
        __syncthreads();
    }

#pragma unroll
    for (int i = 0; i < 4; i++) {
        l[i] += __shfl_xor_sync(0xffffffffu, l[i], 1);
        l[i] += __shfl_xor_sync(0xffffffffu, l[i], 2);
    }
#pragma unroll
    for (int mt = 0; mt < 2; mt++) {
        float inv0 = 1.0f / l[mt * 2 + 0];
        float inv1 = 1.0f / l[mt * 2 + 1];
        int n0 = nb + warp * 32 + mt * 16 + gq;
#pragma unroll
        for (int ht = 0; ht < 2; ht++) {
            int h = d * 16 + ht * 8 + 2 * tg;
            float2 a, b;
            a.x = __uint_as_float(f2tf32(xacc[mt][ht][0] * inv0));
            a.y = __uint_as_float(f2tf32(xacc[mt][ht][1] * inv0));
            b.x = __uint_as_float(f2tf32(xacc[mt][ht][2] * inv1));
            b.y = __uint_as_float(f2tf32(xacc[mt][ht][3] * inv1));
            *(float2*)&XT[(size_t)n0 * DMODEL + h]       = a;
            *(float2*)&XT[(size_t)(n0 + 8) * DMODEL + h] = b;
        }
    }
}

// ---------------- launch ----------------
extern "C" void kernel_launch(void* const* d_in, const int* in_sizes, int n_in,
                              void* d_out, int out_size) {
    (void)in_sizes; (void)n_in; (void)out_size;

    const float* desc0 = (const float*)d_in[0];
    const float* desc1 = (const float*)d_in[1];
    const float* Wq = (const float*)d_in[2]; const float* bq = (const float*)d_in[3];
    const float* Wk = (const float*)d_in[4]; const float* bk = (const float*)d_in[5];
    const float* Wv = (const float*)d_in[6]; const float* bv = (const float*)d_in[7];
    const float* Wm = (const float*)d_in[8]; const float* bm = (const float*)d_in[9];

    float* out0 = (float*)d_out;
    float* out1 = out0 + MN;

    float *Qb, *Kb, *Vb, *Xb, *Wt, *Dt, *Tt;
    cudaGetSymbolAddress((void**)&Qb, g_Q);
    cudaGetSymbolAddress((void**)&Kb, g_K);
    cudaGetSymbolAddress((void**)&Vb, g_V);
    cudaGetSymbolAddress((void**)&Xb, g_X);
    cudaGetSymbolAddress((void**)&Wt, g_W);
    cudaGetSymbolAddress((void**)&Dt, g_D);
    cudaGetSymbolAddress((void**)&Tt, g_T);

    float* W0 = Wt;           float* W1 = Wt + MN;
    float* W2 = Wt + 2 * MN;  float* W3 = Wt + 3 * MN;
    float* D0 = Dt;           float* D1 = Dt + MN;
    float* T0 = Tt;           float* T1 = Tt + MN;

    cudaFuncSetAttribute(conv_gemm, cudaFuncAttributeMaxDynamicSharedMemorySize, SMEM_CONV);
    cudaFuncSetAttribute(conv_gemm, cudaFuncAttributePreferredSharedMemoryCarveout,
                         cudaSharedmemCarveoutMaxShared);
    cudaFuncSetAttribute(flash_kernel, cudaFuncAttributeMaxDynamicSharedMemorySize, SMEM_FLASH);
    cudaFuncSetAttribute(flash_kernel, cudaFuncAttributePreferredSharedMemoryCarveout,
                         cudaSharedmemCarveoutMaxShared);

    // ---- prep
    CvtBatch cb{};
    cb.s[0] = Wq; cb.d[0] = W0;
    cb.s[1] = Wk; cb.d[1] = W1;
    cb.s[2] = Wv; cb.d[2] = W2;
    cb.s[3] = Wm; cb.d[3] = W3;
    prep_round<<<dim3(1024, 4), 256>>>(cb);
    CvtTBatch ct{};
    ct.s[0] = desc0; ct.d[0] = D0;
    ct.s[1] = desc1; ct.d[1] = D1;
    prep_round_T<<<dim3(32, 32, 2), 256>>>(ct);

    // ---- attn1 (desc0 self) + attn2 (desc1 self): QKV GEMMs
    GemmBatch A{};
    A.g[0] = {W0, bq, D0, nullptr, Qb, nullptr};
    A.g[1] = {W1, bk, D0, nullptr, Kb, nullptr};
    A.g[2] = {W2, bv, D0, nullptr, Vb, nullptr};
    A.g[3] = {W0, bq, D1, nullptr, Qb + MN, nullptr};
    A.g[4] = {W1, bk, D1, nullptr, Kb + MN, nullptr};
    A.g[5] = {W2, bv, D1, nullptr, Vb + MN, nullptr};
    conv_gemm<<<dim3(16, 8, 6), 256, SMEM_CONV>>>(A);

    flash_kernel<<<dim3(64, 4, 2), 256, SMEM_FLASH>>>(Qb, Kb, Vb, Xb);

    // d0 = desc0 + Wm@X0 + bm ; d1 = desc1 + Wm@X1 + bm
    GemmBatch C{};
    C.g[0] = {W3, bm, Xb,      desc0, out0, T0};
    C.g[1] = {W3, bm, Xb + MN, desc1, out1, T1};
    conv_gemm<<<dim3(16, 8, 2), 256, SMEM_CONV>>>(C);

    // ---- attn3: q=d0, kv=d1
    GemmBatch Dq{};
    Dq.g[0] = {W0, bq, T0, nullptr, Qb, nullptr};
    Dq.g[1] = {W1, bk, T1, nullptr, Kb, nullptr};
    Dq.g[2] = {W2, bv, T1, nullptr, Vb, nullptr};
    conv_gemm<<<dim3(16, 8, 3), 256, SMEM_CONV>>>(Dq);

    flash_kernel<<<dim3(64, 4, 1), 256, SMEM_FLASH>>>(Qb, Kb, Vb, Xb);

    // ---- F (d0 += conv(x), refresh T0) merged with attn4's Q GEMM (needs only T1)
    GemmBatch FG{};
    FG.g[0] = {W3, bm, Xb, out0, out0, T0};
    FG.g[1] = {W0, bq, T1, nullptr, Qb, nullptr};
    conv_gemm<<<dim3(16, 8, 2), 256, SMEM_CONV>>>(FG);

    // ---- attn4 K,V GEMMs (need T0 from F)
    GemmBatch G{};
    G.g[0] = {W1, bk, T0, nullptr, Kb, nullptr};
    G.g[1] = {W2, bv, T0, nullptr, Vb, nullptr};
    conv_gemm<<<dim3(16, 8, 2), 256, SMEM_CONV>>>(G);

    flash_kernel<<<dim3(64, 4, 1), 256, SMEM_FLASH>>>(Qb, Kb, Vb, Xb);

    GemmBatch I{};
    I.g[0] = {W3, bm, Xb, out1, out1, nullptr};
    conv_gemm<<<dim3(16, 8, 1), 256, SMEM_CONV>>>(I);
}

// round 10
// speedup vs baseline: 2.8564x; 1.0579x over previous
#include <cuda_runtime.h>
#include <cstdint>

#define DMODEL 1024
#define NSEQ   1024
static const int MN = DMODEL * NSEQ;

// ---------------- scratch (device globals; no allocs allowed) ----------------
__device__ float g_Q[2 * 1024 * 1024];
__device__ float g_K[2 * 1024 * 1024];
__device__ float g_V[2 * 1024 * 1024];
__device__ float g_X[2 * 1024 * 1024];   // X^T per item: [n][c], tf32-clean
__device__ float g_W[4 * 1024 * 1024];   // tf32-rounded weights [m][k]
__device__ float g_D[2 * 1024 * 1024];   // desc0^T/desc1^T tf32-rounded [n][c]
__device__ float g_T[2 * 1024 * 1024];   // out0^T/out1^T tf32 mirrors [n][c]

__device__ __forceinline__ uint32_t f2tf32(float f) {
    uint32_t r;
    asm("cvt.rna.tf32.f32 %0, %1;" : "=r"(r) : "f"(f));
    return r;
}
__device__ __forceinline__ float ex2f(float x) {
    float y;
    asm("ex2.approx.f32 %0, %1;" : "=f"(y) : "f"(x));
    return y;
}
__device__ __forceinline__ void mma_tf32(float* d, const uint32_t* a, uint32_t b0, uint32_t b1) {
    asm volatile(
        "mma.sync.aligned.m16n8k8.row.col.f32.tf32.tf32.f32 "
        "{%0,%1,%2,%3}, {%4,%5,%6,%7}, {%8,%9}, {%0,%1,%2,%3};"
        : "+f"(d[0]), "+f"(d[1]), "+f"(d[2]), "+f"(d[3])
        : "r"(a[0]), "r"(a[1]), "r"(a[2]), "r"(a[3]), "r"(b0), "r"(b1));
}
__device__ __forceinline__ void ldsm4(uint32_t& r0, uint32_t& r1, uint32_t& r2, uint32_t& r3,
                                      uint32_t addr) {
    asm volatile("ldmatrix.sync.aligned.m8n8.x4.shared.b16 {%0,%1,%2,%3}, [%4];"
                 : "=r"(r0), "=r"(r1), "=r"(r2), "=r"(r3) : "r"(addr));
}
__device__ __forceinline__ void cp16(uint32_t dst, const void* src) {
    asm volatile("cp.async.cg.shared.global [%0], [%1], 16;" :: "r"(dst), "l"(src));
}
#define CP_COMMIT() asm volatile("cp.async.commit_group;")
#define CP_WAIT0()  asm volatile("cp.async.wait_group 0;")

// ---------------- prep: tf32-round weights; transpose+round descs ------------
struct CvtBatch { const float* s[4]; float* d[4]; };

__global__ __launch_bounds__(256) void prep_round(CvtBatch cb) {
    const float4* s = (const float4*)cb.s[blockIdx.y];
    uint4*        d = (uint4*)cb.d[blockIdx.y];
    int i = blockIdx.x * 256 + threadIdx.x;
    float4 v = s[i];
    uint4 u;
    u.x = f2tf32(v.x); u.y = f2tf32(v.y); u.z = f2tf32(v.z); u.w = f2tf32(v.w);
    d[i] = u;
}

struct CvtTBatch { const float* s[2]; float* d[2]; };

// dst[n][c] = tf32(src[c][n])
__global__ __launch_bounds__(256) void prep_round_T(CvtTBatch cb) {
    __shared__ float t[32][33];
    const float* src = cb.s[blockIdx.z];
    float*       dst = cb.d[blockIdx.z];
    int tx = threadIdx.x & 31, ty = threadIdx.x >> 5;
    int cb0 = blockIdx.y * 32, nb0 = blockIdx.x * 32;
#pragma unroll
    for (int j = 0; j < 4; j++)
        t[ty + j * 8][tx] = src[(size_t)(cb0 + ty + j * 8) * NSEQ + nb0 + tx];
    __syncthreads();
#pragma unroll
    for (int j = 0; j < 4; j++)
        dst[(size_t)(nb0 + ty + j * 8) * DMODEL + cb0 + tx] =
            __uint_as_float(f2tf32(t[tx][ty + j * 8]));
}

// ---------------- tf32 GEMM: 64x128 tile, BK=64, 2-stage double buffer ------
// Y[m,n] = sum_k W[m,k] * Bt[n,k] + bias[m] (+R).  W [m][k], Bt [n][k].
// 16 mainloop iterations; 48KB/stage; 2 CTAs/SM.

struct GemmDesc { const float *W, *bias, *X, *R; float *Y, *Ytf; };
struct GemmBatch { GemmDesc g[6]; };

constexpr int BK = 64;
constexpr int ROWB = 256;                  // bytes per smem row (64 tf32)
constexpr int ASZ = 64 * ROWB;             // 16384
constexpr int BSZ = 128 * ROWB;            // 32768
constexpr int STG = ASZ + BSZ;             // 49152
constexpr int SMEM_CONV = 2 * STG;         // 98304

__global__ __launch_bounds__(256, 2) void conv_gemm(GemmBatch batch) {
    const GemmDesc gd = batch.g[blockIdx.z];
    extern __shared__ char smem[];
    const uint32_t sbase = (uint32_t)__cvta_generic_to_shared(smem);

    const int tid  = threadIdx.x;
    const int lane = tid & 31;
    const int warp = tid >> 5;
    const int gq   = lane >> 2;
    const int tg   = lane & 3;
    const int wm   = (warp >> 2) * 32;
    const int wn   = (warp & 3) * 32;
    const int bm0  = blockIdx.x * 64;
    const int bn0  = blockIdx.y * 128;

    float acc[2][4][4];
#pragma unroll
    for (int mi = 0; mi < 2; mi++)
#pragma unroll
        for (int ni = 0; ni < 4; ni++)
#pragma unroll
            for (int r = 0; r < 4; r++) acc[mi][ni][r] = 0.f;

    const int lj = lane >> 3;
    const int lr = lane & 7;
    uint32_t aoff[2];
#pragma unroll
    for (int mi = 0; mi < 2; mi++)
        aoff[mi] = (uint32_t)(wm + mi * 16 + (lj & 1) * 8 + lr) * ROWB;
    const int akc = lj >> 1;
    uint32_t boff[2];
#pragma unroll
    for (int g = 0; g < 2; g++)
        boff[g] = (uint32_t)(wn + g * 16 + (lj >> 1) * 8 + lr) * ROWB;
    const int bkc = lj & 1;

    // stage loader: 64 k-cols (16 chunks of 16B per row)
    auto load_stage = [&](int stg, int k0) {
        uint32_t A = sbase + stg * STG;
        uint32_t B = A + ASZ;
#pragma unroll
        for (int j = 0; j < 4; j++) {              // A: 1024 chunks
            int idx = tid + j * 256;
            int r = idx >> 4, c = idx & 15;
            cp16(A + r * ROWB + ((c ^ (r & 7)) << 4),
                 gd.W + (size_t)(bm0 + r) * DMODEL + k0 + c * 4);
        }
#pragma unroll
        for (int j = 0; j < 8; j++) {              // B: 2048 chunks
            int idx = tid + j * 256;
            int r = idx >> 4, c = idx & 15;
            cp16(B + r * ROWB + ((c ^ (r & 7)) << 4),
                 gd.X + (size_t)(bn0 + r) * DMODEL + k0 + c * 4);
        }
    };

    load_stage(0, 0);
    CP_COMMIT();

#pragma unroll 1
    for (int i = 0; i < 16; i++) {
        const int s = i & 1;
        CP_WAIT0();                 // current stage resident
        __syncthreads();            // prev compute done everywhere (safe to overwrite other buf)

        if (i < 15) load_stage(s ^ 1, (i + 1) * BK);
        CP_COMMIT();

        const uint32_t A = sbase + s * STG;
        const uint32_t B = A + ASZ;
#pragma unroll
        for (int kk = 0; kk < BK; kk += 8) {
            const int kc = kk >> 2;
            uint32_t af[2][4], bf[4][2];
#pragma unroll
            for (int mi = 0; mi < 2; mi++)
                ldsm4(af[mi][0], af[mi][1], af[mi][2], af[mi][3],
                      A + aoff[mi] + (((kc + akc) ^ lr) << 4));
#pragma unroll
            for (int g = 0; g < 2; g++)
                ldsm4(bf[g * 2][0], bf[g * 2][1], bf[g * 2 + 1][0], bf[g * 2 + 1][1],
                      B + boff[g] + (((kc + bkc) ^ lr) << 4));
#pragma unroll
            for (int mi = 0; mi < 2; mi++)
#pragma unroll
                for (int ni = 0; ni < 4; ni++)
                    mma_tf32(acc[mi][ni], af[mi], bf[ni][0], bf[ni][1]);
        }
    }

#pragma unroll
    for (int mi = 0; mi < 2; mi++) {
        int row0 = bm0 + wm + mi * 16 + gq;
        int row1 = row0 + 8;
        float b0 = gd.bias[row0], b1 = gd.bias[row1];
#pragma unroll
        for (int ni = 0; ni < 4; ni++) {
            int col = bn0 + wn + ni * 8 + tg * 2;
            size_t i0 = (size_t)row0 * NSEQ + col;
            size_t i1 = (size_t)row1 * NSEQ + col;
            float v00 = acc[mi][ni][0] + b0, v01 = acc[mi][ni][1] + b0;
            float v10 = acc[mi][ni][2] + b1, v11 = acc[mi][ni][3] + b1;
            if (gd.R) {
                v00 += gd.R[i0]; v01 += gd.R[i0 + 1];
                v10 += gd.R[i1]; v11 += gd.R[i1 + 1];
            }
            gd.Y[i0] = v00; gd.Y[i0 + 1] = v01;
            gd.Y[i1] = v10; gd.Y[i1 + 1] = v11;
            if (gd.Ytf) {
                gd.Ytf[(size_t)(col + 0) * DMODEL + row0] = __uint_as_float(f2tf32(v00));
                gd.Ytf[(size_t)(col + 1) * DMODEL + row0] = __uint_as_float(f2tf32(v01));
                gd.Ytf[(size_t)(col + 0) * DMODEL + row1] = __uint_as_float(f2tf32(v10));
                gd.Ytf[(size_t)(col + 1) * DMODEL + row1] = __uint_as_float(f2tf32(v11));
            }
        }
    }
}

// ---------------- flash attention: split-KV (2 x 512 cols), 3 CTAs/SM -------
// Output TRANSPOSED per item: XT[n][d*16+h], tf32-clean.

#define QSCALE (0.125f * 1.4426950408889634f)   // 1/sqrt(64) * log2(e)
constexpr int HC = 512;                          // columns per KV pass
constexpr int SMEM_FLASH = 2 * 16 * HC * 4;      // 65536 B

__global__ __launch_bounds__(256) void flash_kernel(const float* __restrict__ Qb,
                                                    const float* __restrict__ Kb,
                                                    const float* __restrict__ Vb,
                                                    float* __restrict__ XTb) {
    extern __shared__ uint32_t fsm[];
    uint32_t* Ks = fsm;                  // [16][512] tf32 bits, swizzled
    uint32_t* Vs = fsm + 16 * HC;

    const int item = blockIdx.z;
    const int d    = blockIdx.x;
    const int nb   = blockIdx.y * 256;
    const int tid  = threadIdx.x;
    const int warp = tid >> 5;
    const int lane = tid & 31;
    const int gq   = lane >> 2;
    const int tg   = lane & 3;

    const float* Qg = Qb + (size_t)item * MN + (size_t)(d * 16) * NSEQ;
    const float* Kg = Kb + (size_t)item * MN + (size_t)(d * 16) * NSEQ;
    const float* Vg = Vb + (size_t)item * MN + (size_t)(d * 16) * NSEQ;
    float*       XT = XTb + (size_t)item * MN;

    uint32_t qf[2][2][4];
#pragma unroll
    for (int mt = 0; mt < 2; mt++) {
        int n0 = nb + warp * 32 + mt * 16 + gq;
#pragma unroll
        for (int ks = 0; ks < 2; ks++) {
            int h = ks * 8 + tg;
            qf[mt][ks][0] = f2tf32(Qg[(size_t)h * NSEQ + n0] * QSCALE);
            qf[mt][ks][1] = f2tf32(Qg[(size_t)h * NSEQ + n0 + 8] * QSCALE);
            qf[mt][ks][2] = f2tf32(Qg[(size_t)(h + 4) * NSEQ + n0] * QSCALE);
            qf[mt][ks][3] = f2tf32(Qg[(size_t)(h + 4) * NSEQ + n0 + 8] * QSCALE);
        }
    }

    float xacc[2][2][4];
#pragma unroll
    for (int mt = 0; mt < 2; mt++)
#pragma unroll
        for (int ht = 0; ht < 2; ht++)
#pragma unroll
            for (int r = 0; r < 4; r++) xacc[mt][ht][r] = 0.f;
    float l[4] = {0.f, 0.f, 0.f, 0.f};

#pragma unroll 1
    for (int half = 0; half < 2; half++) {
#pragma unroll
        for (int j = 0; j < 8; j++) {
            int idx = tid + j * 256;
            int h = idx >> 7;
            int m4 = idx & 127;
            int c = (m4 * 4) ^ ((h & 3) << 3);
            const float4 kv = *(const float4*)&Kg[(size_t)h * NSEQ + half * HC + m4 * 4];
            uint4 u;
            u.x = f2tf32(kv.x); u.y = f2tf32(kv.y); u.z = f2tf32(kv.z); u.w = f2tf32(kv.w);
            *(uint4*)&Ks[h * HC + c] = u;
            const float4 vv = *(const float4*)&Vg[(size_t)h * NSEQ + half * HC + m4 * 4];
            uint4 w;
            w.x = f2tf32(vv.x); w.y = f2tf32(vv.y); w.z = f2tf32(vv.z); w.w = f2tf32(vv.w);
            *(uint4*)&Vs[h * HC + c] = w;
        }
        __syncthreads();

#pragma unroll 2
        for (int m0 = 0; m0 < HC; m0 += 8) {
            int cm = (m0 + gq) ^ (tg << 3);
            uint32_t kf0 = Ks[tg * HC + cm];
            uint32_t kf1 = Ks[(tg + 4) * HC + cm];
            uint32_t kf2 = Ks[(tg + 8) * HC + cm];
            uint32_t kf3 = Ks[(tg + 12) * HC + cm];

            int cv = (m0 + 2 * tg) ^ ((gq & 3) << 3);
            uint2 vf0 = *(const uint2*)&Vs[gq * HC + cv];
            uint2 vf1 = *(const uint2*)&Vs[(8 + gq) * HC + cv];

#pragma unroll
            for (int mt = 0; mt < 2; mt++) {
                float s[4] = {0.f, 0.f, 0.f, 0.f};
                mma_tf32(s, qf[mt][0], kf0, kf1);
                mma_tf32(s, qf[mt][1], kf2, kf3);

                float p0 = ex2f(s[0]), p1 = ex2f(s[1]), p2 = ex2f(s[2]), p3 = ex2f(s[3]);
                l[mt * 2 + 0] += p0 + p1;
                l[mt * 2 + 1] += p2 + p3;

                uint32_t pa[4];
                pa[0] = __float_as_uint(p0); pa[1] = __float_as_uint(p2);
                pa[2] = __float_as_uint(p1); pa[3] = __float_as_uint(p3);

                mma_tf32(xacc[mt][0], pa, vf0.x, vf0.y);
                mma_tf32(xacc[mt][1], pa, vf1.x, vf1.y);
            }
        }
        __syncthreads();
    }

#pragma unroll
    for (int i = 0; i < 4; i++) {
        l[i] += __shfl_xor_sync(0xffffffffu, l[i], 1);
        l[i] += __shfl_xor_sync(0xffffffffu, l[i], 2);
    }
#pragma unroll
    for (int mt = 0; mt < 2; mt++) {
        float inv0 = 1.0f / l[mt * 2 + 0];
        float inv1 = 1.0f / l[mt * 2 + 1];
        int n0 = nb + warp * 32 + mt * 16 + gq;
#pragma unroll
        for (int ht = 0; ht < 2; ht++) {
            int h = d * 16 + ht * 8 + 2 * tg;
            float2 a, b;
            a.x = __uint_as_float(f2tf32(xacc[mt][ht][0] * inv0));
            a.y = __uint_as_float(f2tf32(xacc[mt][ht][1] * inv0));
            b.x = __uint_as_float(f2tf32(xacc[mt][ht][2] * inv1));
            b.y = __uint_as_float(f2tf32(xacc[mt][ht][3] * inv1));
            *(float2*)&XT[(size_t)n0 * DMODEL + h]       = a;
            *(float2*)&XT[(size_t)(n0 + 8) * DMODEL + h] = b;
        }
    }
}

// ---------------- launch ----------------
extern "C" void kernel_launch(void* const* d_in, const int* in_sizes, int n_in,
                              void* d_out, int out_size) {
    (void)in_sizes; (void)n_in; (void)out_size;

    const float* desc0 = (const float*)d_in[0];
    const float* desc1 = (const float*)d_in[1];
    const float* Wq = (const float*)d_in[2]; const float* bq = (const float*)d_in[3];
    const float* Wk = (const float*)d_in[4]; const float* bk = (const float*)d_in[5];
    const float* Wv = (const float*)d_in[6]; const float* bv = (const float*)d_in[7];
    const float* Wm = (const float*)d_in[8]; const float* bm = (const float*)d_in[9];

    float* out0 = (float*)d_out;
    float* out1 = out0 + MN;

    float *Qb, *Kb, *Vb, *Xb, *Wt, *Dt, *Tt;
    cudaGetSymbolAddress((void**)&Qb, g_Q);
    cudaGetSymbolAddress((void**)&Kb, g_K);
    cudaGetSymbolAddress((void**)&Vb, g_V);
    cudaGetSymbolAddress((void**)&Xb, g_X);
    cudaGetSymbolAddress((void**)&Wt, g_W);
    cudaGetSymbolAddress((void**)&Dt, g_D);
    cudaGetSymbolAddress((void**)&Tt, g_T);

    float* W0 = Wt;           float* W1 = Wt + MN;
    float* W2 = Wt + 2 * MN;  float* W3 = Wt + 3 * MN;
    float* D0 = Dt;           float* D1 = Dt + MN;
    float* T0 = Tt;           float* T1 = Tt + MN;

    cudaFuncSetAttribute(conv_gemm, cudaFuncAttributeMaxDynamicSharedMemorySize, SMEM_CONV);
    cudaFuncSetAttribute(conv_gemm, cudaFuncAttributePreferredSharedMemoryCarveout,
                         cudaSharedmemCarveoutMaxShared);
    cudaFuncSetAttribute(flash_kernel, cudaFuncAttributeMaxDynamicSharedMemorySize, SMEM_FLASH);
    cudaFuncSetAttribute(flash_kernel, cudaFuncAttributePreferredSharedMemoryCarveout,
                         cudaSharedmemCarveoutMaxShared);

    // ---- prep
    CvtBatch cb{};
    cb.s[0] = Wq; cb.d[0] = W0;
    cb.s[1] = Wk; cb.d[1] = W1;
    cb.s[2] = Wv; cb.d[2] = W2;
    cb.s[3] = Wm; cb.d[3] = W3;
    prep_round<<<dim3(1024, 4), 256>>>(cb);
    CvtTBatch ct{};
    ct.s[0] = desc0; ct.d[0] = D0;
    ct.s[1] = desc1; ct.d[1] = D1;
    prep_round_T<<<dim3(32, 32, 2), 256>>>(ct);

    // ---- attn1 (desc0 self) + attn2 (desc1 self): QKV GEMMs
    GemmBatch A{};
    A.g[0] = {W0, bq, D0, nullptr, Qb, nullptr};
    A.g[1] = {W1, bk, D0, nullptr, Kb, nullptr};
    A.g[2] = {W2, bv, D0, nullptr, Vb, nullptr};
    A.g[3] = {W0, bq, D1, nullptr, Qb + MN, nullptr};
    A.g[4] = {W1, bk, D1, nullptr, Kb + MN, nullptr};
    A.g[5] = {W2, bv, D1, nullptr, Vb + MN, nullptr};
    conv_gemm<<<dim3(16, 8, 6), 256, SMEM_CONV>>>(A);

    flash_kernel<<<dim3(64, 4, 2), 256, SMEM_FLASH>>>(Qb, Kb, Vb, Xb);

    // d0 = desc0 + Wm@X0 + bm ; d1 = desc1 + Wm@X1 + bm
    GemmBatch C{};
    C.g[0] = {W3, bm, Xb,      desc0, out0, T0};
    C.g[1] = {W3, bm, Xb + MN, desc1, out1, T1};
    conv_gemm<<<dim3(16, 8, 2), 256, SMEM_CONV>>>(C);

    // ---- attn3: q=d0, kv=d1
    GemmBatch Dq{};
    Dq.g[0] = {W0, bq, T0, nullptr, Qb, nullptr};
    Dq.g[1] = {W1, bk, T1, nullptr, Kb, nullptr};
    Dq.g[2] = {W2, bv, T1, nullptr, Vb, nullptr};
    conv_gemm<<<dim3(16, 8, 3), 256, SMEM_CONV>>>(Dq);

    flash_kernel<<<dim3(64, 4, 1), 256, SMEM_FLASH>>>(Qb, Kb, Vb, Xb);

    // ---- F (d0 += conv(x), refresh T0) merged with attn4's Q GEMM (needs only T1)
    GemmBatch FG{};
    FG.g[0] = {W3, bm, Xb, out0, out0, T0};
    FG.g[1] = {W0, bq, T1, nullptr, Qb, nullptr};
    conv_gemm<<<dim3(16, 8, 2), 256, SMEM_CONV>>>(FG);

    // ---- attn4 K,V GEMMs (need T0 from F)
    GemmBatch G{};
    G.g[0] = {W1, bk, T0, nullptr, Kb, nullptr};
    G.g[1] = {W2, bv, T0, nullptr, Vb, nullptr};
    conv_gemm<<<dim3(16, 8, 2), 256, SMEM_CONV>>>(G);

    flash_kernel<<<dim3(64, 4, 1), 256, SMEM_FLASH>>>(Qb, Kb, Vb, Xb);

    GemmBatch I{};
    I.g[0] = {W3, bm, Xb, out1, out1, nullptr};
    conv_gemm<<<dim3(16, 8, 1), 256, SMEM_CONV>>>(I);
}

// round 11
// speedup vs baseline: 3.7902x; 1.3269x over previous
#include <cuda_runtime.h>
#include <cuda_bf16.h>
#include <cstdint>

#define DMODEL 1024
#define NSEQ   1024
static const int MN = DMODEL * NSEQ;

// ---------------- scratch (device globals; no allocs allowed) ----------------
__device__ float g_Q[2 * 1024 * 1024];
__device__ float g_K[2 * 1024 * 1024];
__device__ float g_V[2 * 1024 * 1024];
__device__ __nv_bfloat16 g_X[2 * 1024 * 1024];   // X^T per item: [n][c] bf16
__device__ __nv_bfloat16 g_W[4 * 1024 * 1024];   // weights bf16 [m][k]
__device__ __nv_bfloat16 g_D[2 * 1024 * 1024];   // desc^T bf16 [n][c]
__device__ __nv_bfloat16 g_T[2 * 1024 * 1024];   // out^T bf16 mirrors [n][c]

__device__ __forceinline__ uint32_t f2tf32(float f) {
    uint32_t r;
    asm("cvt.rna.tf32.f32 %0, %1;" : "=r"(r) : "f"(f));
    return r;
}
__device__ __forceinline__ float ex2f(float x) {
    float y;
    asm("ex2.approx.f32 %0, %1;" : "=f"(y) : "f"(x));
    return y;
}
__device__ __forceinline__ void mma_tf32(float* d, const uint32_t* a, uint32_t b0, uint32_t b1) {
    asm volatile(
        "mma.sync.aligned.m16n8k8.row.col.f32.tf32.tf32.f32 "
        "{%0,%1,%2,%3}, {%4,%5,%6,%7}, {%8,%9}, {%0,%1,%2,%3};"
        : "+f"(d[0]), "+f"(d[1]), "+f"(d[2]), "+f"(d[3])
        : "r"(a[0]), "r"(a[1]), "r"(a[2]), "r"(a[3]), "r"(b0), "r"(b1));
}
__device__ __forceinline__ void mma_bf16(float* d, const uint32_t* a, uint32_t b0, uint32_t b1) {
    asm volatile(
        "mma.sync.aligned.m16n8k16.row.col.f32.bf16.bf16.f32 "
        "{%0,%1,%2,%3}, {%4,%5,%6,%7}, {%8,%9}, {%0,%1,%2,%3};"
        : "+f"(d[0]), "+f"(d[1]), "+f"(d[2]), "+f"(d[3])
        : "r"(a[0]), "r"(a[1]), "r"(a[2]), "r"(a[3]), "r"(b0), "r"(b1));
}
__device__ __forceinline__ void ldsm4(uint32_t& r0, uint32_t& r1, uint32_t& r2, uint32_t& r3,
                                      uint32_t addr) {
    asm volatile("ldmatrix.sync.aligned.m8n8.x4.shared.b16 {%0,%1,%2,%3}, [%4];"
                 : "=r"(r0), "=r"(r1), "=r"(r2), "=r"(r3) : "r"(addr));
}
__device__ __forceinline__ void cp16(uint32_t dst, const void* src) {
    asm volatile("cp.async.cg.shared.global [%0], [%1], 16;" :: "r"(dst), "l"(src));
}
#define CP_COMMIT() asm volatile("cp.async.commit_group;")
#define CP_WAIT0()  asm volatile("cp.async.wait_group 0;")

__device__ __forceinline__ __nv_bfloat162 bf2(float lo, float hi) {
    __nv_bfloat162 t;
    t.x = __float2bfloat16_rn(lo);
    t.y = __float2bfloat16_rn(hi);
    return t;
}

// ---------------- prep: bf16-round weights; transpose+round descs ------------
struct CvtBatch { const float* s[4]; __nv_bfloat16* d[4]; };

__global__ __launch_bounds__(256) void prep_round(CvtBatch cb) {
    const float4* s = (const float4*)cb.s[blockIdx.y];
    __nv_bfloat162* d = (__nv_bfloat162*)cb.d[blockIdx.y];
    int i = blockIdx.x * 256 + threadIdx.x;
    float4 v = s[i];
    d[2 * i]     = bf2(v.x, v.y);
    d[2 * i + 1] = bf2(v.z, v.w);
}

struct CvtTBatch { const float* s[2]; __nv_bfloat16* d[2]; };

// dst[n][c] = bf16(src[c][n])
__global__ __launch_bounds__(256) void prep_round_T(CvtTBatch cb) {
    __shared__ float t[32][33];
    const float* src = cb.s[blockIdx.z];
    __nv_bfloat16* dst = cb.d[blockIdx.z];
    int tx = threadIdx.x & 31, ty = threadIdx.x >> 5;
    int cb0 = blockIdx.y * 32, nb0 = blockIdx.x * 32;
#pragma unroll
    for (int j = 0; j < 4; j++)
        t[ty + j * 8][tx] = src[(size_t)(cb0 + ty + j * 8) * NSEQ + nb0 + tx];
    __syncthreads();
#pragma unroll
    for (int j = 0; j < 4; j++)
        dst[(size_t)(nb0 + ty + j * 8) * DMODEL + cb0 + tx] =
            __float2bfloat16_rn(t[tx][ty + j * 8]);
}

// ---------------- bf16 GEMM: 64x128 tile, BK=128, 2-stage double buffer -----
// Y[m,n] = sum_k W[m,k] * Bt[n,k] + bias[m] (+R).  W [m][k] bf16, Bt [n][k] bf16.
// 8 mainloop iterations; 48KB/stage; 2 CTAs/SM.

struct GemmDesc { const __nv_bfloat16 *W; const float *bias; const __nv_bfloat16 *X;
                  const float *R; float *Y; __nv_bfloat16 *Ytf; };
struct GemmBatch { GemmDesc g[6]; };

constexpr int BK = 128;
constexpr int ROWB = 256;                  // bytes per smem row (128 bf16)
constexpr int ASZ = 64 * ROWB;             // 16384
constexpr int BSZ = 128 * ROWB;            // 32768
constexpr int STG = ASZ + BSZ;             // 49152
constexpr int SMEM_CONV = 2 * STG;         // 98304

__global__ __launch_bounds__(256, 2) void conv_gemm(GemmBatch batch) {
    const GemmDesc gd = batch.g[blockIdx.z];
    extern __shared__ char smem[];
    const uint32_t sbase = (uint32_t)__cvta_generic_to_shared(smem);

    const int tid  = threadIdx.x;
    const int lane = tid & 31;
    const int warp = tid >> 5;
    const int gq   = lane >> 2;
    const int tg   = lane & 3;
    const int wm   = (warp >> 2) * 32;
    const int wn   = (warp & 3) * 32;
    const int bm0  = blockIdx.x * 64;
    const int bn0  = blockIdx.y * 128;

    float acc[2][4][4];
#pragma unroll
    for (int mi = 0; mi < 2; mi++)
#pragma unroll
        for (int ni = 0; ni < 4; ni++)
#pragma unroll
            for (int r = 0; r < 4; r++) acc[mi][ni][r] = 0.f;

    const int lj = lane >> 3;          // matrix index 0..3
    const int lr = lane & 7;           // row within matrix
    // A (m16n8k16 frag): r0=(m0-7,k0-7) r1=(m8-15,k0-7) r2=(m0-7,k8-15) r3=(m8-15,k8-15)
    uint32_t aoff[2];
#pragma unroll
    for (int mi = 0; mi < 2; mi++)
        aoff[mi] = (uint32_t)(wm + mi * 16 + (lj & 1) * 8 + lr) * ROWB;
    const int akc = lj >> 1;           // +kchunk
    // B frag: r0=b0(ni even) r1=b1(ni even) r2=b0(ni odd) r3=b1(ni odd)
    uint32_t boff[2];
#pragma unroll
    for (int g = 0; g < 2; g++)
        boff[g] = (uint32_t)(wn + g * 16 + (lj >> 1) * 8 + lr) * ROWB;
    const int bkc = lj & 1;

    // stage loader: 128 k-cols = 16 chunks of 16B (8 bf16) per row
    auto load_stage = [&](int stg, int k0) {
        uint32_t A = sbase + stg * STG;
        uint32_t B = A + ASZ;
#pragma unroll
        for (int j = 0; j < 4; j++) {              // A: 1024 chunks
            int idx = tid + j * 256;
            int r = idx >> 4, c = idx & 15;
            cp16(A + r * ROWB + ((c ^ (r & 7)) << 4),
                 gd.W + (size_t)(bm0 + r) * DMODEL + k0 + c * 8);
        }
#pragma unroll
        for (int j = 0; j < 8; j++) {              // B: 2048 chunks
            int idx = tid + j * 256;
            int r = idx >> 4, c = idx & 15;
            cp16(B + r * ROWB + ((c ^ (r & 7)) << 4),
                 gd.X + (size_t)(bn0 + r) * DMODEL + k0 + c * 8);
        }
    };

    load_stage(0, 0);
    CP_COMMIT();

#pragma unroll 1
    for (int i = 0; i < 8; i++) {
        const int s = i & 1;
        CP_WAIT0();
        __syncthreads();

        if (i < 7) load_stage(s ^ 1, (i + 1) * BK);
        CP_COMMIT();

        const uint32_t A = sbase + s * STG;
        const uint32_t B = A + ASZ;
#pragma unroll
        for (int ks = 0; ks < 8; ks++) {           // 8 k16-steps of BK=128
            uint32_t af[2][4], bf[4][2];
#pragma unroll
            for (int mi = 0; mi < 2; mi++)
                ldsm4(af[mi][0], af[mi][1], af[mi][2], af[mi][3],
                      A + aoff[mi] + (((2 * ks + akc) ^ lr) << 4));
#pragma unroll
            for (int g = 0; g < 2; g++)
                ldsm4(bf[g * 2][0], bf[g * 2][1], bf[g * 2 + 1][0], bf[g * 2 + 1][1],
                      B + boff[g] + (((2 * ks + bkc) ^ lr) << 4));
#pragma unroll
            for (int mi = 0; mi < 2; mi++)
#pragma unroll
                for (int ni = 0; ni < 4; ni++)
                    mma_bf16(acc[mi][ni], af[mi], bf[ni][0], bf[ni][1]);
        }
    }

#pragma unroll
    for (int mi = 0; mi < 2; mi++) {
        int row0 = bm0 + wm + mi * 16 + gq;
        int row1 = row0 + 8;
        float b0 = gd.bias[row0], b1 = gd.bias[row1];
#pragma unroll
        for (int ni = 0; ni < 4; ni++) {
            int col = bn0 + wn + ni * 8 + tg * 2;
            size_t i0 = (size_t)row0 * NSEQ + col;
            size_t i1 = (size_t)row1 * NSEQ + col;
            float v00 = acc[mi][ni][0] + b0, v01 = acc[mi][ni][1] + b0;
            float v10 = acc[mi][ni][2] + b1, v11 = acc[mi][ni][3] + b1;
            if (gd.R) {
                v00 += gd.R[i0]; v01 += gd.R[i0 + 1];
                v10 += gd.R[i1]; v11 += gd.R[i1 + 1];
            }
            gd.Y[i0] = v00; gd.Y[i0 + 1] = v01;
            gd.Y[i1] = v10; gd.Y[i1 + 1] = v11;
            if (gd.Ytf) {
                gd.Ytf[(size_t)(col + 0) * DMODEL + row0] = __float2bfloat16_rn(v00);
                gd.Ytf[(size_t)(col + 1) * DMODEL + row0] = __float2bfloat16_rn(v01);
                gd.Ytf[(size_t)(col + 0) * DMODEL + row1] = __float2bfloat16_rn(v10);
                gd.Ytf[(size_t)(col + 1) * DMODEL + row1] = __float2bfloat16_rn(v11);
            }
        }
    }
}

// ---------------- flash attention: split-KV (2 x 512 cols), 3 CTAs/SM -------
// tf32 internal; output TRANSPOSED bf16: XT[n][d*16+h].

#define QSCALE (0.125f * 1.4426950408889634f)   // 1/sqrt(64) * log2(e)
constexpr int HC = 512;                          // columns per KV pass
constexpr int SMEM_FLASH = 2 * 16 * HC * 4;      // 65536 B

__global__ __launch_bounds__(256) void flash_kernel(const float* __restrict__ Qb,
                                                    const float* __restrict__ Kb,
                                                    const float* __restrict__ Vb,
                                                    __nv_bfloat16* __restrict__ XTb) {
    extern __shared__ uint32_t fsm[];
    uint32_t* Ks = fsm;                  // [16][512] tf32 bits, swizzled
    uint32_t* Vs = fsm + 16 * HC;

    const int item = blockIdx.z;
    const int d    = blockIdx.x;
    const int nb   = blockIdx.y * 256;
    const int tid  = threadIdx.x;
    const int warp = tid >> 5;
    const int lane = tid & 31;
    const int gq   = lane >> 2;
    const int tg   = lane & 3;

    const float* Qg = Qb + (size_t)item * MN + (size_t)(d * 16) * NSEQ;
    const float* Kg = Kb + (size_t)item * MN + (size_t)(d * 16) * NSEQ;
    const float* Vg = Vb + (size_t)item * MN + (size_t)(d * 16) * NSEQ;
    __nv_bfloat16* XT = XTb + (size_t)item * MN;

    uint32_t qf[2][2][4];
#pragma unroll
    for (int mt = 0; mt < 2; mt++) {
        int n0 = nb + warp * 32 + mt * 16 + gq;
#pragma unroll
        for (int ks = 0; ks < 2; ks++) {
            int h = ks * 8 + tg;
            qf[mt][ks][0] = f2tf32(Qg[(size_t)h * NSEQ + n0] * QSCALE);
            qf[mt][ks][1] = f2tf32(Qg[(size_t)h * NSEQ + n0 + 8] * QSCALE);
            qf[mt][ks][2] = f2tf32(Qg[(size_t)(h + 4) * NSEQ + n0] * QSCALE);
            qf[mt][ks][3] = f2tf32(Qg[(size_t)(h + 4) * NSEQ + n0 + 8] * QSCALE);
        }
    }

    float xacc[2][2][4];
#pragma unroll
    for (int mt = 0; mt < 2; mt++)
#pragma unroll
        for (int ht = 0; ht < 2; ht++)
#pragma unroll
            for (int r = 0; r < 4; r++) xacc[mt][ht][r] = 0.f;
    float l[4] = {0.f, 0.f, 0.f, 0.f};

#pragma unroll 1
    for (int half = 0; half < 2; half++) {
#pragma unroll
        for (int j = 0; j < 8; j++) {
            int idx = tid + j * 256;
            int h = idx >> 7;
            int m4 = idx & 127;
            int c = (m4 * 4) ^ ((h & 3) << 3);
            const float4 kv = *(const float4*)&Kg[(size_t)h * NSEQ + half * HC + m4 * 4];
            uint4 u;
            u.x = f2tf32(kv.x); u.y = f2tf32(kv.y); u.z = f2tf32(kv.z); u.w = f2tf32(kv.w);
            *(uint4*)&Ks[h * HC + c] = u;
            const float4 vv = *(const float4*)&Vg[(size_t)h * NSEQ + half * HC + m4 * 4];
            uint4 w;
            w.x = f2tf32(vv.x); w.y = f2tf32(vv.y); w.z = f2tf32(vv.z); w.w = f2tf32(vv.w);
            *(uint4*)&Vs[h * HC + c] = w;
        }
        __syncthreads();

#pragma unroll 2
        for (int m0 = 0; m0 < HC; m0 += 8) {
            int cm = (m0 + gq) ^ (tg << 3);
            uint32_t kf0 = Ks[tg * HC + cm];
            uint32_t kf1 = Ks[(tg + 4) * HC + cm];
            uint32_t kf2 = Ks[(tg + 8) * HC + cm];
            uint32_t kf3 = Ks[(tg + 12) * HC + cm];

            int cv = (m0 + 2 * tg) ^ ((gq & 3) << 3);
            uint2 vf0 = *(const uint2*)&Vs[gq * HC + cv];
            uint2 vf1 = *(const uint2*)&Vs[(8 + gq) * HC + cv];

#pragma unroll
            for (int mt = 0; mt < 2; mt++) {
                float s[4] = {0.f, 0.f, 0.f, 0.f};
                mma_tf32(s, qf[mt][0], kf0, kf1);
                mma_tf32(s, qf[mt][1], kf2, kf3);

                float p0 = ex2f(s[0]), p1 = ex2f(s[1]), p2 = ex2f(s[2]), p3 = ex2f(s[3]);
                l[mt * 2 + 0] += p0 + p1;
                l[mt * 2 + 1] += p2 + p3;

                uint32_t pa[4];
                pa[0] = __float_as_uint(p0); pa[1] = __float_as_uint(p2);
                pa[2] = __float_as_uint(p1); pa[3] = __float_as_uint(p3);

                mma_tf32(xacc[mt][0], pa, vf0.x, vf0.y);
                mma_tf32(xacc[mt][1], pa, vf1.x, vf1.y);
            }
        }
        __syncthreads();
    }

#pragma unroll
    for (int i = 0; i < 4; i++) {
        l[i] += __shfl_xor_sync(0xffffffffu, l[i], 1);
        l[i] += __shfl_xor_sync(0xffffffffu, l[i], 2);
    }
#pragma unroll
    for (int mt = 0; mt < 2; mt++) {
        float inv0 = 1.0f / l[mt * 2 + 0];
        float inv1 = 1.0f / l[mt * 2 + 1];
        int n0 = nb + warp * 32 + mt * 16 + gq;
#pragma unroll
        for (int ht = 0; ht < 2; ht++) {
            int h = d * 16 + ht * 8 + 2 * tg;      // even -> 4B aligned bf162 store
            *(__nv_bfloat162*)&XT[(size_t)n0 * DMODEL + h] =
                bf2(xacc[mt][ht][0] * inv0, xacc[mt][ht][1] * inv0);
            *(__nv_bfloat162*)&XT[(size_t)(n0 + 8) * DMODEL + h] =
                bf2(xacc[mt][ht][2] * inv1, xacc[mt][ht][3] * inv1);
        }
    }
}

// ---------------- launch ----------------
extern "C" void kernel_launch(void* const* d_in, const int* in_sizes, int n_in,
                              void* d_out, int out_size) {
    (void)in_sizes; (void)n_in; (void)out_size;

    const float* desc0 = (const float*)d_in[0];
    const float* desc1 = (const float*)d_in[1];
    const float* Wq = (const float*)d_in[2]; const float* bq = (const float*)d_in[3];
    const float* Wk = (const float*)d_in[4]; const float* bk = (const float*)d_in[5];
    const float* Wv = (const float*)d_in[6]; const float* bv = (const float*)d_in[7];
    const float* Wm = (const float*)d_in[8]; const float* bm = (const float*)d_in[9];

    float* out0 = (float*)d_out;
    float* out1 = out0 + MN;

    float *Qb, *Kb, *Vb;
    __nv_bfloat16 *Xb, *Wt, *Dt, *Tt;
    cudaGetSymbolAddress((void**)&Qb, g_Q);
    cudaGetSymbolAddress((void**)&Kb, g_K);
    cudaGetSymbolAddress((void**)&Vb, g_V);
    cudaGetSymbolAddress((void**)&Xb, g_X);
    cudaGetSymbolAddress((void**)&Wt, g_W);
    cudaGetSymbolAddress((void**)&Dt, g_D);
    cudaGetSymbolAddress((void**)&Tt, g_T);

    __nv_bfloat16* W0 = Wt;           __nv_bfloat16* W1 = Wt + MN;
    __nv_bfloat16* W2 = Wt + 2 * MN;  __nv_bfloat16* W3 = Wt + 3 * MN;
    __nv_bfloat16* D0 = Dt;           __nv_bfloat16* D1 = Dt + MN;
    __nv_bfloat16* T0 = Tt;           __nv_bfloat16* T1 = Tt + MN;

    cudaFuncSetAttribute(conv_gemm, cudaFuncAttributeMaxDynamicSharedMemorySize, SMEM_CONV);
    cudaFuncSetAttribute(conv_gemm, cudaFuncAttributePreferredSharedMemoryCarveout,
                         cudaSharedmemCarveoutMaxShared);
    cudaFuncSetAttribute(flash_kernel, cudaFuncAttributeMaxDynamicSharedMemorySize, SMEM_FLASH);
    cudaFuncSetAttribute(flash_kernel, cudaFuncAttributePreferredSharedMemoryCarveout,
                         cudaSharedmemCarveoutMaxShared);

    // ---- prep
    CvtBatch cb{};
    cb.s[0] = Wq; cb.d[0] = W0;
    cb.s[1] = Wk; cb.d[1] = W1;
    cb.s[2] = Wv; cb.d[2] = W2;
    cb.s[3] = Wm; cb.d[3] = W3;
    prep_round<<<dim3(1024, 4), 256>>>(cb);
    CvtTBatch ct{};
    ct.s[0] = desc0; ct.d[0] = D0;
    ct.s[1] = desc1; ct.d[1] = D1;
    prep_round_T<<<dim3(32, 32, 2), 256>>>(ct);

    // ---- attn1 (desc0 self) + attn2 (desc1 self): QKV GEMMs
    GemmBatch A{};
    A.g[0] = {W0, bq, D0, nullptr, Qb, nullptr};
    A.g[1] = {W1, bk, D0, nullptr, Kb, nullptr};
    A.g[2] = {W2, bv, D0, nullptr, Vb, nullptr};
    A.g[3] = {W0, bq, D1, nullptr, Qb + MN, nullptr};
    A.g[4] = {W1, bk, D1, nullptr, Kb + MN, nullptr};
    A.g[5] = {W2, bv, D1, nullptr, Vb + MN, nullptr};
    conv_gemm<<<dim3(16, 8, 6), 256, SMEM_CONV>>>(A);

    flash_kernel<<<dim3(64, 4, 2), 256, SMEM_FLASH>>>(Qb, Kb, Vb, Xb);

    // d0 = desc0 + Wm@X0 + bm ; d1 = desc1 + Wm@X1 + bm
    GemmBatch C{};
    C.g[0] = {W3, bm, Xb,      desc0, out0, T0};
    C.g[1] = {W3, bm, Xb + MN, desc1, out1, T1};
    conv_gemm<<<dim3(16, 8, 2), 256, SMEM_CONV>>>(C);

    // ---- attn3: q=d0, kv=d1
    GemmBatch Dq{};
    Dq.g[0] = {W0, bq, T0, nullptr, Qb, nullptr};
    Dq.g[1] = {W1, bk, T1, nullptr, Kb, nullptr};
    Dq.g[2] = {W2, bv, T1, nullptr, Vb, nullptr};
    conv_gemm<<<dim3(16, 8, 3), 256, SMEM_CONV>>>(Dq);

    flash_kernel<<<dim3(64, 4, 1), 256, SMEM_FLASH>>>(Qb, Kb, Vb, Xb);

    // ---- F (d0 += conv(x), refresh T0) merged with attn4's Q GEMM (needs only T1)
    GemmBatch FG{};
    FG.g[0] = {W3, bm, Xb, out0, out0, T0};
    FG.g[1] = {W0, bq, T1, nullptr, Qb, nullptr};
    conv_gemm<<<dim3(16, 8, 2), 256, SMEM_CONV>>>(FG);

    // ---- attn4 K,V GEMMs (need T0 from F)
    GemmBatch G{};
    G.g[0] = {W1, bk, T0, nullptr, Kb, nullptr};
    G.g[1] = {W2, bv, T0, nullptr, Vb, nullptr};
    conv_gemm<<<dim3(16, 8, 2), 256, SMEM_CONV>>>(G);

    flash_kernel<<<dim3(64, 4, 1), 256, SMEM_FLASH>>>(Qb, Kb, Vb, Xb);

    GemmBatch I{};
    I.g[0] = {W3, bm, Xb, out1, out1, nullptr};
    conv_gemm<<<dim3(16, 8, 1), 256, SMEM_CONV>>>(I);
}

// round 12
// speedup vs baseline: 4.2840x; 1.1303x over previous
#include <cuda_runtime.h>
#include <cuda_bf16.h>
#include <cstdint>

#define DMODEL 1024
#define NSEQ   1024
static const int MN = DMODEL * NSEQ;

// ---------------- scratch (device globals; no allocs allowed) ----------------
__device__ __nv_bfloat16 g_Q[2 * 1024 * 1024];   // Q [c][n] bf16
__device__ __nv_bfloat16 g_K[2 * 1024 * 1024];   // K [c][n] bf16
__device__ __nv_bfloat16 g_V[2 * 1024 * 1024];   // V [c][n] bf16
__device__ __nv_bfloat16 g_X[2 * 1024 * 1024];   // X^T per item: [n][c] bf16
__device__ __nv_bfloat16 g_W[4 * 1024 * 1024];   // weights bf16 [m][k]
__device__ __nv_bfloat16 g_D[2 * 1024 * 1024];   // desc^T bf16 [n][c]
__device__ __nv_bfloat16 g_T[2 * 1024 * 1024];   // out^T bf16 mirrors [n][c]

__device__ __forceinline__ float ex2f(float x) {
    float y;
    asm("ex2.approx.f32 %0, %1;" : "=f"(y) : "f"(x));
    return y;
}
__device__ __forceinline__ void mma_bf16(float* d, const uint32_t* a, uint32_t b0, uint32_t b1) {
    asm volatile(
        "mma.sync.aligned.m16n8k16.row.col.f32.bf16.bf16.f32 "
        "{%0,%1,%2,%3}, {%4,%5,%6,%7}, {%8,%9}, {%0,%1,%2,%3};"
        : "+f"(d[0]), "+f"(d[1]), "+f"(d[2]), "+f"(d[3])
        : "r"(a[0]), "r"(a[1]), "r"(a[2]), "r"(a[3]), "r"(b0), "r"(b1));
}
__device__ __forceinline__ void ldsm4(uint32_t& r0, uint32_t& r1, uint32_t& r2, uint32_t& r3,
                                      uint32_t addr) {
    asm volatile("ldmatrix.sync.aligned.m8n8.x4.shared.b16 {%0,%1,%2,%3}, [%4];"
                 : "=r"(r0), "=r"(r1), "=r"(r2), "=r"(r3) : "r"(addr));
}
__device__ __forceinline__ void cp16(uint32_t dst, const void* src) {
    asm volatile("cp.async.cg.shared.global [%0], [%1], 16;" :: "r"(dst), "l"(src));
}
#define CP_COMMIT() asm volatile("cp.async.commit_group;")
#define CP_WAIT0()  asm volatile("cp.async.wait_group 0;")

__device__ __forceinline__ __nv_bfloat162 bf2(float lo, float hi) {
    __nv_bfloat162 t;
    t.x = __float2bfloat16_rn(lo);
    t.y = __float2bfloat16_rn(hi);
    return t;
}
__device__ __forceinline__ uint32_t packbf(float lo, float hi) {
    uint32_t r;
    asm("cvt.rn.bf16x2.f32 %0, %1, %2;" : "=r"(r) : "f"(hi), "f"(lo));
    return r;
}

// ---------------- prep: bf16-round weights; transpose+round descs ------------
struct CvtBatch { const float* s[4]; __nv_bfloat16* d[4]; };

__global__ __launch_bounds__(256) void prep_round(CvtBatch cb) {
    const float4* s = (const float4*)cb.s[blockIdx.y];
    __nv_bfloat162* d = (__nv_bfloat162*)cb.d[blockIdx.y];
    int i = blockIdx.x * 256 + threadIdx.x;
    float4 v = s[i];
    d[2 * i]     = bf2(v.x, v.y);
    d[2 * i + 1] = bf2(v.z, v.w);
}

struct CvtTBatch { const float* s[2]; __nv_bfloat16* d[2]; };

// dst[n][c] = bf16(src[c][n])
__global__ __launch_bounds__(256) void prep_round_T(CvtTBatch cb) {
    __shared__ float t[32][33];
    const float* src = cb.s[blockIdx.z];
    __nv_bfloat16* dst = cb.d[blockIdx.z];
    int tx = threadIdx.x & 31, ty = threadIdx.x >> 5;
    int cb0 = blockIdx.y * 32, nb0 = blockIdx.x * 32;
#pragma unroll
    for (int j = 0; j < 4; j++)
        t[ty + j * 8][tx] = src[(size_t)(cb0 + ty + j * 8) * NSEQ + nb0 + tx];
    __syncthreads();
#pragma unroll
    for (int j = 0; j < 4; j++)
        dst[(size_t)(nb0 + ty + j * 8) * DMODEL + cb0 + tx] =
            __float2bfloat16_rn(t[tx][ty + j * 8]);
}

// ---------------- bf16 GEMM: 64x128 tile, BK=128, 2-stage double buffer -----
// Y[m,n] = sum_k W[m,k] * Bt[n,k] + bias[m] (+R).
// Outputs: fp32 Y and/or bf16 Ybf (same layout) and/or bf16 Ytf (transposed).

struct GemmDesc { const __nv_bfloat16 *W; const float *bias; const __nv_bfloat16 *X;
                  const float *R; float *Y; __nv_bfloat16 *Ytf; __nv_bfloat16 *Ybf; };
struct GemmBatch { GemmDesc g[6]; };

constexpr int BK = 128;
constexpr int ROWB = 256;                  // bytes per smem row (128 bf16)
constexpr int ASZ = 64 * ROWB;             // 16384
constexpr int BSZ = 128 * ROWB;            // 32768
constexpr int STG = ASZ + BSZ;             // 49152
constexpr int SMEM_CONV = 2 * STG;         // 98304

__global__ __launch_bounds__(256, 2) void conv_gemm(GemmBatch batch) {
    const GemmDesc gd = batch.g[blockIdx.z];
    extern __shared__ char smem[];
    const uint32_t sbase = (uint32_t)__cvta_generic_to_shared(smem);

    const int tid  = threadIdx.x;
    const int lane = tid & 31;
    const int warp = tid >> 5;
    const int gq   = lane >> 2;
    const int tg   = lane & 3;
    const int wm   = (warp >> 2) * 32;
    const int wn   = (warp & 3) * 32;
    const int bm0  = blockIdx.x * 64;
    const int bn0  = blockIdx.y * 128;

    float acc[2][4][4];
#pragma unroll
    for (int mi = 0; mi < 2; mi++)
#pragma unroll
        for (int ni = 0; ni < 4; ni++)
#pragma unroll
            for (int r = 0; r < 4; r++) acc[mi][ni][r] = 0.f;

    const int lj = lane >> 3;
    const int lr = lane & 7;
    uint32_t aoff[2];
#pragma unroll
    for (int mi = 0; mi < 2; mi++)
        aoff[mi] = (uint32_t)(wm + mi * 16 + (lj & 1) * 8 + lr) * ROWB;
    const int akc = lj >> 1;
    uint32_t boff[2];
#pragma unroll
    for (int g = 0; g < 2; g++)
        boff[g] = (uint32_t)(wn + g * 16 + (lj >> 1) * 8 + lr) * ROWB;
    const int bkc = lj & 1;

    auto load_stage = [&](int stg, int k0) {
        uint32_t A = sbase + stg * STG;
        uint32_t B = A + ASZ;
#pragma unroll
        for (int j = 0; j < 4; j++) {
            int idx = tid + j * 256;
            int r = idx >> 4, c = idx & 15;
            cp16(A + r * ROWB + ((c ^ (r & 7)) << 4),
                 gd.W + (size_t)(bm0 + r) * DMODEL + k0 + c * 8);
        }
#pragma unroll
        for (int j = 0; j < 8; j++) {
            int idx = tid + j * 256;
            int r = idx >> 4, c = idx & 15;
            cp16(B + r * ROWB + ((c ^ (r & 7)) << 4),
                 gd.X + (size_t)(bn0 + r) * DMODEL + k0 + c * 8);
        }
    };

    load_stage(0, 0);
    CP_COMMIT();

#pragma unroll 1
    for (int i = 0; i < 8; i++) {
        const int s = i & 1;
        CP_WAIT0();
        __syncthreads();

        if (i < 7) load_stage(s ^ 1, (i + 1) * BK);
        CP_COMMIT();

        const uint32_t A = sbase + s * STG;
        const uint32_t B = A + ASZ;
#pragma unroll
        for (int ks = 0; ks < 8; ks++) {
            uint32_t af[2][4], bf[4][2];
#pragma unroll
            for (int mi = 0; mi < 2; mi++)
                ldsm4(af[mi][0], af[mi][1], af[mi][2], af[mi][3],
                      A + aoff[mi] + (((2 * ks + akc) ^ lr) << 4));
#pragma unroll
            for (int g = 0; g < 2; g++)
                ldsm4(bf[g * 2][0], bf[g * 2][1], bf[g * 2 + 1][0], bf[g * 2 + 1][1],
                      B + boff[g] + (((2 * ks + bkc) ^ lr) << 4));
#pragma unroll
            for (int mi = 0; mi < 2; mi++)
#pragma unroll
                for (int ni = 0; ni < 4; ni++)
                    mma_bf16(acc[mi][ni], af[mi], bf[ni][0], bf[ni][1]);
        }
    }

#pragma unroll
    for (int mi = 0; mi < 2; mi++) {
        int row0 = bm0 + wm + mi * 16 + gq;
        int row1 = row0 + 8;
        float b0 = gd.bias[row0], b1 = gd.bias[row1];
#pragma unroll
        for (int ni = 0; ni < 4; ni++) {
            int col = bn0 + wn + ni * 8 + tg * 2;
            size_t i0 = (size_t)row0 * NSEQ + col;
            size_t i1 = (size_t)row1 * NSEQ + col;
            float v00 = acc[mi][ni][0] + b0, v01 = acc[mi][ni][1] + b0;
            float v10 = acc[mi][ni][2] + b1, v11 = acc[mi][ni][3] + b1;
            if (gd.R) {
                v00 += gd.R[i0]; v01 += gd.R[i0 + 1];
                v10 += gd.R[i1]; v11 += gd.R[i1 + 1];
            }
            if (gd.Y) {
                gd.Y[i0] = v00; gd.Y[i0 + 1] = v01;
                gd.Y[i1] = v10; gd.Y[i1 + 1] = v11;
            }
            if (gd.Ybf) {
                *(__nv_bfloat162*)&gd.Ybf[i0] = bf2(v00, v01);
                *(__nv_bfloat162*)&gd.Ybf[i1] = bf2(v10, v11);
            }
            if (gd.Ytf) {
                gd.Ytf[(size_t)(col + 0) * DMODEL + row0] = __float2bfloat16_rn(v00);
                gd.Ytf[(size_t)(col + 1) * DMODEL + row0] = __float2bfloat16_rn(v01);
                gd.Ytf[(size_t)(col + 0) * DMODEL + row1] = __float2bfloat16_rn(v10);
                gd.Ytf[(size_t)(col + 1) * DMODEL + row1] = __float2bfloat16_rn(v11);
            }
        }
    }
}

// ---------------- bf16 flash attention: split-KV (2 x 512), 4 CTAs/SM -------
// QK: m16n8k16 (k = 16 heads, one mma). PV: m16n8k16 over m (S C-frags pack
// directly into the k16 A-frag). K staged h-paired bf16x2; V staged [h][m] bf16.
// Output TRANSPOSED bf16: XT[n][d*16+h].

#define QSCALE (0.125f * 1.4426950408889634f)   // 1/sqrt(64) * log2(e)
constexpr int HC = 512;                          // columns per KV pass
constexpr int SMEM_FLASH = 32768;                // Ks2 16KB + Vs 16KB

__global__ __launch_bounds__(256, 4) void flash_kernel(const __nv_bfloat16* __restrict__ Qb,
                                                       const __nv_bfloat16* __restrict__ Kb,
                                                       const __nv_bfloat16* __restrict__ Vb,
                                                       __nv_bfloat16* __restrict__ XTb) {
    extern __shared__ uint32_t fsm[];
    uint32_t* Ks2 = fsm;             // [8][512] words: (K[2h2][m], K[2h2+1][m]); 16B-chunk swizzle ^((h2&3)<<1)
    uint32_t* Vs  = fsm + 8 * 512;   // [16][256] words: bf16 pairs (m,m+1); 16B-chunk swizzle ^(h&7)

    const int item = blockIdx.z;
    const int d    = blockIdx.x;
    const int nb   = blockIdx.y * 256;
    const int tid  = threadIdx.x;
    const int warp = tid >> 5;
    const int lane = tid & 31;
    const int gq   = lane >> 2;
    const int tg   = lane & 3;

    const __nv_bfloat16* Qg = Qb + (size_t)item * MN + (size_t)(d * 16) * NSEQ;
    const __nv_bfloat16* Kg = Kb + (size_t)item * MN + (size_t)(d * 16) * NSEQ;
    const __nv_bfloat16* Vg = Vb + (size_t)item * MN + (size_t)(d * 16) * NSEQ;
    __nv_bfloat16* XT = XTb + (size_t)item * MN;

    // Q A-fragments (m16n8k16, k = 16 heads), QSCALE folded
    uint32_t qf[2][4];
#pragma unroll
    for (int mt = 0; mt < 2; mt++) {
        int n0 = nb + warp * 32 + mt * 16 + gq;
        int h0 = 2 * tg;
#pragma unroll
        for (int kb = 0; kb < 2; kb++) {        // kb=0: h0, kb=1: h0+8
            int h = h0 + kb * 8;
            float a0 = __bfloat162float(Qg[(size_t)h * NSEQ + n0]) * QSCALE;
            float a1 = __bfloat162float(Qg[(size_t)(h + 1) * NSEQ + n0]) * QSCALE;
            float b0 = __bfloat162float(Qg[(size_t)h * NSEQ + n0 + 8]) * QSCALE;
            float b1 = __bfloat162float(Qg[(size_t)(h + 1) * NSEQ + n0 + 8]) * QSCALE;
            qf[mt][kb * 2 + 0] = packbf(a0, a1);   // rows gq
            qf[mt][kb * 2 + 1] = packbf(b0, b1);   // rows gq+8
        }
    }

    float xacc[2][2][4];
#pragma unroll
    for (int mt = 0; mt < 2; mt++)
#pragma unroll
        for (int ht = 0; ht < 2; ht++)
#pragma unroll
            for (int r = 0; r < 4; r++) xacc[mt][ht][r] = 0.f;
    float l[4] = {0.f, 0.f, 0.f, 0.f};

#pragma unroll 1
    for (int half = 0; half < 2; half++) {
        // ---- K fill: 1024 16B-chunks (h-paired via byte_perm)
#pragma unroll
        for (int j = 0; j < 4; j++) {
            int idx = tid + j * 256;
            int h2 = idx >> 7;
            int mc = idx & 127;
            int m = half * HC + mc * 4;
            uint2 uA = *(const uint2*)(Kg + (size_t)(2 * h2) * NSEQ + m);
            uint2 uB = *(const uint2*)(Kg + (size_t)(2 * h2 + 1) * NSEQ + m);
            uint4 o;
            o.x = __byte_perm(uA.x, uB.x, 0x5410);
            o.y = __byte_perm(uA.x, uB.x, 0x7632);
            o.z = __byte_perm(uA.y, uB.y, 0x5410);
            o.w = __byte_perm(uA.y, uB.y, 0x7632);
            *(uint4*)(Ks2 + h2 * 512 + ((mc ^ ((h2 & 3) << 1)) << 2)) = o;
        }
        // ---- V fill: 1024 16B-chunks, straight copy
#pragma unroll
        for (int j = 0; j < 4; j++) {
            int idx = tid + j * 256;
            int h = idx >> 6;
            int mc = idx & 63;
            int m = half * HC + mc * 8;
            uint4 v = *(const uint4*)(Vg + (size_t)h * NSEQ + m);
            *(uint4*)(Vs + h * 256 + ((mc ^ (h & 7)) << 2)) = v;
        }
        __syncthreads();

#pragma unroll 1
        for (int m0 = 0; m0 < HC; m0 += 16) {
            // K B-frags (k = heads): block0 m0+gq, block1 m0+8+gq
            int w0 = m0 + gq, w1 = w0 + 8;
            int ks = tg << 1;
            uint32_t kb00 = Ks2[tg * 512 + (((w0 >> 2) ^ ks) << 2) + (w0 & 3)];
            uint32_t kb01 = Ks2[(tg + 4) * 512 + (((w0 >> 2) ^ ks) << 2) + (w0 & 3)];
            uint32_t kb10 = Ks2[tg * 512 + (((w1 >> 2) ^ ks) << 2) + (w1 & 3)];
            uint32_t kb11 = Ks2[(tg + 4) * 512 + (((w1 >> 2) ^ ks) << 2) + (w1 & 3)];

            // V B-frags (k = m): pairs at m0+2tg (chunk c0) and m0+8+2tg (chunk c0+1)
            int c0 = m0 >> 3;
            uint32_t vb00 = Vs[gq * 256 + ((c0 ^ gq) << 2) + tg];
            uint32_t vb01 = Vs[gq * 256 + (((c0 + 1) ^ gq) << 2) + tg];
            uint32_t vb10 = Vs[(8 + gq) * 256 + ((c0 ^ gq) << 2) + tg];
            uint32_t vb11 = Vs[(8 + gq) * 256 + (((c0 + 1) ^ gq) << 2) + tg];

#pragma unroll
            for (int mt = 0; mt < 2; mt++) {
                float s0[4] = {0.f, 0.f, 0.f, 0.f};
                float s1[4] = {0.f, 0.f, 0.f, 0.f};
                mma_bf16(s0, qf[mt], kb00, kb01);
                mma_bf16(s1, qf[mt], kb10, kb11);

                float p00 = ex2f(s0[0]), p01 = ex2f(s0[1]);
                float p02 = ex2f(s0[2]), p03 = ex2f(s0[3]);
                float p10 = ex2f(s1[0]), p11 = ex2f(s1[1]);
                float p12 = ex2f(s1[2]), p13 = ex2f(s1[3]);
                l[mt * 2 + 0] += (p00 + p01) + (p10 + p11);
                l[mt * 2 + 1] += (p02 + p03) + (p12 + p13);

                uint32_t pa[4];
                pa[0] = packbf(p00, p01);   // (gq,   k=m0+2tg, +1)
                pa[1] = packbf(p02, p03);   // (gq+8, k=m0+2tg, +1)
                pa[2] = packbf(p10, p11);   // (gq,   k=m0+8+2tg, +1)
                pa[3] = packbf(p12, p13);   // (gq+8, ...)

                mma_bf16(xacc[mt][0], pa, vb00, vb01);
                mma_bf16(xacc[mt][1], pa, vb10, vb11);
            }
        }
        __syncthreads();
    }

#pragma unroll
    for (int i = 0; i < 4; i++) {
        l[i] += __shfl_xor_sync(0xffffffffu, l[i], 1);
        l[i] += __shfl_xor_sync(0xffffffffu, l[i], 2);
    }
#pragma unroll
    for (int mt = 0; mt < 2; mt++) {
        float inv0 = 1.0f / l[mt * 2 + 0];
        float inv1 = 1.0f / l[mt * 2 + 1];
        int n0 = nb + warp * 32 + mt * 16 + gq;
#pragma unroll
        for (int ht = 0; ht < 2; ht++) {
            int h = d * 16 + ht * 8 + 2 * tg;      // even -> aligned bf162 store
            *(__nv_bfloat162*)&XT[(size_t)n0 * DMODEL + h] =
                bf2(xacc[mt][ht][0] * inv0, xacc[mt][ht][1] * inv0);
            *(__nv_bfloat162*)&XT[(size_t)(n0 + 8) * DMODEL + h] =
                bf2(xacc[mt][ht][2] * inv1, xacc[mt][ht][3] * inv1);
        }
    }
}

// ---------------- launch ----------------
extern "C" void kernel_launch(void* const* d_in, const int* in_sizes, int n_in,
                              void* d_out, int out_size) {
    (void)in_sizes; (void)n_in; (void)out_size;

    const float* desc0 = (const float*)d_in[0];
    const float* desc1 = (const float*)d_in[1];
    const float* Wq = (const float*)d_in[2]; const float* bq = (const float*)d_in[3];
    const float* Wk = (const float*)d_in[4]; const float* bk = (const float*)d_in[5];
    const float* Wv = (const float*)d_in[6]; const float* bv = (const float*)d_in[7];
    const float* Wm = (const float*)d_in[8]; const float* bm = (const float*)d_in[9];

    float* out0 = (float*)d_out;
    float* out1 = out0 + MN;

    __nv_bfloat16 *Qb, *Kb, *Vb, *Xb, *Wt, *Dt, *Tt;
    cudaGetSymbolAddress((void**)&Qb, g_Q);
    cudaGetSymbolAddress((void**)&Kb, g_K);
    cudaGetSymbolAddress((void**)&Vb, g_V);
    cudaGetSymbolAddress((void**)&Xb, g_X);
    cudaGetSymbolAddress((void**)&Wt, g_W);
    cudaGetSymbolAddress((void**)&Dt, g_D);
    cudaGetSymbolAddress((void**)&Tt, g_T);

    __nv_bfloat16* W0 = Wt;           __nv_bfloat16* W1 = Wt + MN;
    __nv_bfloat16* W2 = Wt + 2 * MN;  __nv_bfloat16* W3 = Wt + 3 * MN;
    __nv_bfloat16* D0 = Dt;           __nv_bfloat16* D1 = Dt + MN;
    __nv_bfloat16* T0 = Tt;           __nv_bfloat16* T1 = Tt + MN;

    cudaFuncSetAttribute(conv_gemm, cudaFuncAttributeMaxDynamicSharedMemorySize, SMEM_CONV);
    cudaFuncSetAttribute(conv_gemm, cudaFuncAttributePreferredSharedMemoryCarveout,
                         cudaSharedmemCarveoutMaxShared);
    cudaFuncSetAttribute(flash_kernel, cudaFuncAttributeMaxDynamicSharedMemorySize, SMEM_FLASH);
    cudaFuncSetAttribute(flash_kernel, cudaFuncAttributePreferredSharedMemoryCarveout,
                         cudaSharedmemCarveoutMaxShared);

    // ---- prep
    CvtBatch cb{};
    cb.s[0] = Wq; cb.d[0] = W0;
    cb.s[1] = Wk; cb.d[1] = W1;
    cb.s[2] = Wv; cb.d[2] = W2;
    cb.s[3] = Wm; cb.d[3] = W3;
    prep_round<<<dim3(1024, 4), 256>>>(cb);
    CvtTBatch ct{};
    ct.s[0] = desc0; ct.d[0] = D0;
    ct.s[1] = desc1; ct.d[1] = D1;
    prep_round_T<<<dim3(32, 32, 2), 256>>>(ct);

    // ---- attn1 (desc0 self) + attn2 (desc1 self): QKV GEMMs -> bf16 direct
    GemmBatch A{};
    A.g[0] = {W0, bq, D0, nullptr, nullptr, nullptr, Qb};
    A.g[1] = {W1, bk, D0, nullptr, nullptr, nullptr, Kb};
    A.g[2] = {W2, bv, D0, nullptr, nullptr, nullptr, Vb};
    A.g[3] = {W0, bq, D1, nullptr, nullptr, nullptr, Qb + MN};
    A.g[4] = {W1, bk, D1, nullptr, nullptr, nullptr, Kb + MN};
    A.g[5] = {W2, bv, D1, nullptr, nullptr, nullptr, Vb + MN};
    conv_gemm<<<dim3(16, 8, 6), 256, SMEM_CONV>>>(A);

    flash_kernel<<<dim3(64, 4, 2), 256, SMEM_FLASH>>>(Qb, Kb, Vb, Xb);

    // d0 = desc0 + Wm@X0 + bm ; d1 = desc1 + Wm@X1 + bm
    GemmBatch C{};
    C.g[0] = {W3, bm, Xb,      desc0, out0, T0, nullptr};
    C.g[1] = {W3, bm, Xb + MN, desc1, out1, T1, nullptr};
    conv_gemm<<<dim3(16, 8, 2), 256, SMEM_CONV>>>(C);

    // ---- attn3: q=d0, kv=d1
    GemmBatch Dq{};
    Dq.g[0] = {W0, bq, T0, nullptr, nullptr, nullptr, Qb};
    Dq.g[1] = {W1, bk, T1, nullptr, nullptr, nullptr, Kb};
    Dq.g[2] = {W2, bv, T1, nullptr, nullptr, nullptr, Vb};
    conv_gemm<<<dim3(16, 8, 3), 256, SMEM_CONV>>>(Dq);

    flash_kernel<<<dim3(64, 4, 1), 256, SMEM_FLASH>>>(Qb, Kb, Vb, Xb);

    // ---- F (d0 += conv(x), refresh T0) merged with attn4's Q GEMM (needs only T1)
    GemmBatch FG{};
    FG.g[0] = {W3, bm, Xb, out0, out0, T0, nullptr};
    FG.g[1] = {W0, bq, T1, nullptr, nullptr, nullptr, Qb};
    conv_gemm<<<dim3(16, 8, 2), 256, SMEM_CONV>>>(FG);

    // ---- attn4 K,V GEMMs (need T0 from F)
    GemmBatch G{};
    G.g[0] = {W1, bk, T0, nullptr, nullptr, nullptr, Kb};
    G.g[1] = {W2, bv, T0, nullptr, nullptr, nullptr, Vb};
    conv_gemm<<<dim3(16, 8, 2), 256, SMEM_CONV>>>(G);

    flash_kernel<<<dim3(64, 4, 1), 256, SMEM_FLASH>>>(Qb, Kb, Vb, Xb);

    GemmBatch I{};
    I.g[0] = {W3, bm, Xb, out1, out1, nullptr, nullptr};
    conv_gemm<<<dim3(16, 8, 1), 256, SMEM_CONV>>>(I);
}